// round 7
// baseline (speedup 1.0000x reference)
#include <cuda_runtime.h>
#include <cuda_bf16.h>
#include <math.h>

#define N_INST 16384
#define NB1    1024
#define NB2    64
#define DIM    1024
#define NATT   256
#define NCLS   512

// ---------------- scratch (device globals; no allocation allowed) ----------
__device__ float g_emb1[N_INST * DIM];   // 64 MB
__device__ float g_emb2[NB1 * DIM];
__device__ float g_emb3[NB2 * DIM];
__device__ float g_s[N_INST + NB1 + NB2];
__device__ float g_stats[8];
// conv2 weights, transposed [n=64][k=800], split into bf16 hi/lo
__device__ __nv_bfloat16 g_w2t_hi[64 * 800];
__device__ __nv_bfloat16 g_w2t_lo[64 * 800];
// embeddings as bf16 hi/lo (for tensor-core attention GEMMs)
__device__ __nv_bfloat16 g_emb1h[N_INST * DIM], g_emb1l[N_INST * DIM];
__device__ __nv_bfloat16 g_emb2h[NB1 * DIM],    g_emb2l[NB1 * DIM];
__device__ __nv_bfloat16 g_emb3h[NB2 * DIM],    g_emb3l[NB2 * DIM];
// attention weights, transposed [n=256][k=1024], hi/lo, 3 levels
__device__ __nv_bfloat16 g_awt_hi[3 * NATT * DIM];
__device__ __nv_bfloat16 g_awt_lo[3 * NATT * DIM];

__device__ __forceinline__ float* emb_buf(int lvl) {
    return lvl == 0 ? g_emb1 : (lvl == 1 ? g_emb2 : g_emb3);
}
__device__ __forceinline__ float* s_buf(int lvl) {
    return lvl == 0 ? g_s : (lvl == 1 ? g_s + N_INST : g_s + N_INST + NB1);
}

// ---------------- mma helpers ----------------------------------------------
__device__ __forceinline__ void ldsm4(unsigned& r0, unsigned& r1, unsigned& r2,
                                      unsigned& r3, unsigned a) {
    asm volatile("ldmatrix.sync.aligned.m8n8.x4.shared.b16 {%0,%1,%2,%3}, [%4];"
                 : "=r"(r0), "=r"(r1), "=r"(r2), "=r"(r3) : "r"(a));
}
__device__ __forceinline__ void mma_bf16(float* c, unsigned a0, unsigned a1,
                                         unsigned a2, unsigned a3,
                                         unsigned b0, unsigned b1) {
    asm volatile(
        "mma.sync.aligned.m16n8k16.row.col.f32.bf16.bf16.f32 "
        "{%0,%1,%2,%3},{%4,%5,%6,%7},{%8,%9},{%0,%1,%2,%3};"
        : "+f"(c[0]), "+f"(c[1]), "+f"(c[2]), "+f"(c[3])
        : "r"(a0), "r"(a1), "r"(a2), "r"(a3), "r"(b0), "r"(b1));
}

// ---------------------------------------------------------------------------
// Prep kernels: weight transposes + bf16 hi/lo splits
// ---------------------------------------------------------------------------
__global__ __launch_bounds__(256) void prep_w2t(const float* __restrict__ w2) {
    const int idx = blockIdx.x * 256 + threadIdx.x;
    if (idx >= 64 * 800) return;
    const int n = idx / 800, k = idx - n * 800;
    const float v = w2[k * 64 + n];
    const __nv_bfloat16 h = __float2bfloat16(v);
    g_w2t_hi[idx] = h;
    g_w2t_lo[idx] = __float2bfloat16(v - __bfloat162float(h));
}

__global__ __launch_bounds__(256) void prep_awt(const float* __restrict__ W, int set) {
    const int idx = blockIdx.x * 256 + threadIdx.x;   // 262144 total
    const int n = idx >> 10, k = idx & 1023;
    const float v = W[k * NATT + n];
    const __nv_bfloat16 h = __float2bfloat16(v);
    g_awt_hi[set * (NATT * DIM) + idx] = h;
    g_awt_lo[set * (NATT * DIM) + idx] = __float2bfloat16(v - __bfloat162float(h));
}

// ---------------------------------------------------------------------------
// Fused conv kernel: one CTA = 1 image, BOTH convs on tensor cores.
// Phase A: conv1 as im2col GEMM C[576,32] = A[576,32] x w1[32,32] (k-pad 25->32),
//   k split into 2 chunks of 16, m split into 2 halves of 288 rows.
//   im2col row order = pooled_pos*4 + member so 2x2 maxpool reduces inside the
//   m16 fragment via shfl_xor(4),shfl_xor(8). Epilogue writes p1 hi/lo planes.
// Phase B: conv2 implicit GEMM (as R6), warps = 4 m-tiles x 2 n-halves.
// smem map (bytes):
//  0      p1h [144*40 bf16]           11520
//  11520  p1l                         11520
//  23040  A region: phaseA Ah(13824)+Al(13824); phaseB slabs hi/lo 43008
//  66048  w1B: 2 chunks x (hi 1536 + lo 1536) = 6144
//  72192  input fp32 784              3136
//  75328  b1 (32 f) / b2 (64 f)       384
// ---------------------------------------------------------------------------
#define SM_P1H   0
#define SM_P1L   11520
#define SM_A     23040
#define SM_BSLAB 23040
#define SM_W1B   66048
#define SM_IN    72192
#define SM_B1    75328
#define SM_B2    75456
#define FC_SMEM  75776

__global__ __launch_bounds__(256, 2) void fused_conv_kernel(
    const float* __restrict__ x,
    const float* __restrict__ w1, const float* __restrict__ b1,
    const float* __restrict__ b2)
{
    extern __shared__ char smem[];
    const unsigned sbase = (unsigned)__cvta_generic_to_shared(smem);
    const int tid = threadIdx.x;
    const int l = tid & 31, w = tid >> 5;

    __nv_bfloat16* Ah  = (__nv_bfloat16*)(smem + SM_A);
    __nv_bfloat16* Alo = (__nv_bfloat16*)(smem + SM_A + 13824);
    __nv_bfloat16* p1h = (__nv_bfloat16*)(smem + SM_P1H);
    __nv_bfloat16* p1l = (__nv_bfloat16*)(smem + SM_P1L);
    float* in_s = (float*)(smem + SM_IN);
    float* b1_s = (float*)(smem + SM_B1);
    float* b2_s = (float*)(smem + SM_B2);

    // stage input, biases, w1 B-chunks (hi/lo, [n=32][k=16] stride 24 elems)
    {
        const float* x0 = x + (size_t)blockIdx.x * 784;
        for (int i = tid; i < 784; i += 256) in_s[i] = x0[i];
        if (tid < 32) b1_s[tid] = b1[tid];
        if (tid < 64) b2_s[tid] = b2[tid];
        for (int i = tid; i < 1024; i += 256) {
            const int kc = i >> 9, c = (i >> 5) & 15, n = i & 31;
            const int tap = kc * 16 + c;
            const float v = (tap < 25) ? w1[tap * 32 + n] : 0.f;
            const __nv_bfloat16 h = __float2bfloat16(v);
            __nv_bfloat16* wb = (__nv_bfloat16*)(smem + SM_W1B + kc * 3072);
            wb[n * 24 + c] = h;
            wb[768 + n * 24 + c] = __float2bfloat16(v - __bfloat162float(h));
        }
    }

    const int lane_r = ((l >> 3) & 1) * 8 + (l & 7);
    const unsigned khalf = ((l >> 4) & 1) * 16;

    // ---------------- Phase A: conv1 via tensor cores ----------------------
    for (int mh = 0; mh < 2; mh++) {
        float acc[3][4][4];
        #pragma unroll
        for (int ti = 0; ti < 3; ti++)
            #pragma unroll
            for (int g = 0; g < 4; g++)
                #pragma unroll
                for (int q = 0; q < 4; q++) acc[ti][g][q] = 0.f;

        for (int kc = 0; kc < 2; kc++) {
            __syncthreads();   // A region free (covers initial staging too)
            // build A chunk: 288 rows x 16 cols, hi/lo
            for (int i = tid; i < 4608; i += 256) {
                const int r = i >> 4, c = i & 15;
                const int tap = kc * 16 + c;
                if (tap < 25) {
                    const int ky = tap / 5, kx = tap - ky * 5;
                    const int rg = mh * 288 + r;
                    const int q = rg >> 2, j = rg & 3;
                    const int qr = q / 12, qc = q - qr * 12;
                    const float v =
                        in_s[(qr * 2 + (j >> 1) + ky) * 28 + qc * 2 + (j & 1) + kx];
                    const __nv_bfloat16 h = __float2bfloat16(v);
                    Ah[r * 24 + c] = h;
                    Alo[r * 24 + c] = __float2bfloat16(v - __bfloat162float(h));
                }
            }
            __syncthreads();

            // B frags (w1) for this chunk: 4 n-tiles x 2 k-halves, hi+lo
            unsigned h0[4], h1[4], q0[4], q1[4];
            const unsigned wb = sbase + SM_W1B + (unsigned)kc * 3072 + (unsigned)l * 48;
            ldsm4(h0[0], h0[1], h0[2], h0[3], wb);
            ldsm4(h1[0], h1[1], h1[2], h1[3], wb + 16);
            ldsm4(q0[0], q0[1], q0[2], q0[3], wb + 1536);
            ldsm4(q1[0], q1[1], q1[2], q1[3], wb + 1536 + 16);

            for (int tl = w, ti = 0; tl < 18; tl += 8, ti++) {
                const unsigned ab =
                    sbase + SM_A + (unsigned)(tl * 16 + lane_r) * 48 + khalf;
                unsigned a0, a1, a2, a3, c0, c1, c2, c3;
                ldsm4(a0, a1, a2, a3, ab);
                ldsm4(c0, c1, c2, c3, ab + 13824);
                #pragma unroll
                for (int g = 0; g < 4; g++) {
                    mma_bf16(acc[ti][g], a0, a1, a2, a3, h0[g], h1[g]);
                    mma_bf16(acc[ti][g], a0, a1, a2, a3, q0[g], q1[g]);
                    mma_bf16(acc[ti][g], c0, c1, c2, c3, h0[g], h1[g]);
                }
            }
        }

        // epilogue: pool over 4 fragment rows + bias + relu -> p1 planes
        for (int tl = w, ti = 0; tl < 18; tl += 8, ti++) {
            const int tg = mh * 18 + tl;
            #pragma unroll
            for (int g = 0; g < 4; g++) {
                float m0 = acc[ti][g][0], m1 = acc[ti][g][1];
                float m2 = acc[ti][g][2], m3 = acc[ti][g][3];
                m0 = fmaxf(m0, __shfl_xor_sync(0xffffffffu, m0, 4));
                m0 = fmaxf(m0, __shfl_xor_sync(0xffffffffu, m0, 8));
                m1 = fmaxf(m1, __shfl_xor_sync(0xffffffffu, m1, 4));
                m1 = fmaxf(m1, __shfl_xor_sync(0xffffffffu, m1, 8));
                m2 = fmaxf(m2, __shfl_xor_sync(0xffffffffu, m2, 4));
                m2 = fmaxf(m2, __shfl_xor_sync(0xffffffffu, m2, 8));
                m3 = fmaxf(m3, __shfl_xor_sync(0xffffffffu, m3, 4));
                m3 = fmaxf(m3, __shfl_xor_sync(0xffffffffu, m3, 8));
                if ((l & 12) == 0) {
                    const int qb = l >> 4;               // 0 -> q0/q2, 1 -> q1/q3
                    const int ch = g * 8 + 2 * (l & 3);
                    const float bA = b1_s[ch], bB = b1_s[ch + 1];
                    const float v0 = fmaxf(m0 + bA, 0.f);
                    const float v1 = fmaxf(m1 + bB, 0.f);
                    const float v2 = fmaxf(m2 + bA, 0.f);
                    const float v3 = fmaxf(m3 + bB, 0.f);
                    const int p0 = tg * 4 + qb, p2 = tg * 4 + 2 + qb;
                    const __nv_bfloat16 h0v = __float2bfloat16(v0);
                    const __nv_bfloat16 h1v = __float2bfloat16(v1);
                    const __nv_bfloat16 h2v = __float2bfloat16(v2);
                    const __nv_bfloat16 h3v = __float2bfloat16(v3);
                    __nv_bfloat162 t0; t0.x = h0v; t0.y = h1v;
                    __nv_bfloat162 t1;
                    t1.x = __float2bfloat16(v0 - __bfloat162float(h0v));
                    t1.y = __float2bfloat16(v1 - __bfloat162float(h1v));
                    __nv_bfloat162 t2; t2.x = h2v; t2.y = h3v;
                    __nv_bfloat162 t3;
                    t3.x = __float2bfloat16(v2 - __bfloat162float(h2v));
                    t3.y = __float2bfloat16(v3 - __bfloat162float(h3v));
                    *(__nv_bfloat162*)&p1h[p0 * 40 + ch] = t0;
                    *(__nv_bfloat162*)&p1l[p0 * 40 + ch] = t1;
                    *(__nv_bfloat162*)&p1h[p2 * 40 + ch] = t2;
                    *(__nv_bfloat162*)&p1l[p2 * 40 + ch] = t3;
                }
            }
        }
    }

    // ---------------- Phase B: conv2 via tensor cores ----------------------
    {
        const int mt = w & 3, nh = w >> 2;
        const int pos = mt * 16 + lane_r;
        const int my = pos >> 3, mx = pos & 7;
        const unsigned aHb = sbase + SM_P1H, aLb = sbase + SM_P1L;
        const unsigned BHb = sbase + SM_BSLAB, BLb = BHb + 21504;

        float acc[4][4];
        #pragma unroll
        for (int j = 0; j < 4; j++)
            #pragma unroll
            for (int q = 0; q < 4; q++) acc[j][q] = 0.f;

        const char* wth = (const char*)g_w2t_hi;
        const char* wtl = (const char*)g_w2t_lo;

        for (int ky = 0; ky < 5; ky++) {
            __syncthreads();   // epilogue/previous slab consumers done
            for (int i = tid; i < 2560; i += 256) {
                const int s  = i >= 1280;
                const int ii = i - s * 1280;
                const int n  = ii / 20, c = ii - n * 20;
                const char* src = (s ? wtl : wth) + n * 1600 + ky * 320 + c * 16;
                char* dst = smem + SM_BSLAB + s * 21504 + n * 336 + c * 16;
                *(uint4*)dst = *(const uint4*)src;
            }
            __syncthreads();

            const unsigned arow = ((my + ky) * 12 + mx) * 80;
            for (int kx = 0; kx < 5; kx++) {
                #pragma unroll
                for (int hf = 0; hf < 2; hf++) {
                    const unsigned ab = arow + kx * 80 + khalf + hf * 32;
                    unsigned ah0, ah1, ah2, ah3, al0, al1, al2, al3;
                    ldsm4(ah0, ah1, ah2, ah3, aHb + ab);
                    ldsm4(al0, al1, al2, al3, aLb + ab);

                    const unsigned kb = (unsigned)(kx * 2 + hf) * 32;
                    const unsigned brow = (unsigned)(nh * 32 + l) * 336 + kb;
                    unsigned bh[8], bl[8];
                    ldsm4(bh[0], bh[1], bh[2], bh[3], BHb + brow);
                    ldsm4(bh[4], bh[5], bh[6], bh[7], BHb + brow + 16);
                    ldsm4(bl[0], bl[1], bl[2], bl[3], BLb + brow);
                    ldsm4(bl[4], bl[5], bl[6], bl[7], BLb + brow + 16);

                    #pragma unroll
                    for (int j = 0; j < 4; j++) {
                        mma_bf16(acc[j], ah0, ah1, ah2, ah3, bh[j], bh[4 + j]);
                        mma_bf16(acc[j], ah0, ah1, ah2, ah3, bl[j], bl[4 + j]);
                        mma_bf16(acc[j], al0, al1, al2, al3, bh[j], bh[4 + j]);
                    }
                }
            }
        }

        // epilogue: 2x2 maxpool + bias + relu -> emb1 (fp32 + bf16 hi/lo)
        const long row_img = blockIdx.x;
        #pragma unroll
        for (int j = 0; j < 4; j++) {
            float v0 = fmaxf(acc[j][0], acc[j][2]);
            float v1 = fmaxf(acc[j][1], acc[j][3]);
            const float u0 = fmaxf(v0, __shfl_down_sync(0xffffffffu, v0, 4));
            const float u1 = fmaxf(v1, __shfl_down_sync(0xffffffffu, v1, 4));
            if (((l >> 2) & 1) == 0) {
                const int pc = l >> 3;
                const int p  = mt * 4 + pc;
                const int nn = nh * 32 + j * 8 + 2 * (l & 3);
                float2 o;
                o.x = fmaxf(u0 + b2_s[nn], 0.f);
                o.y = fmaxf(u1 + b2_s[nn + 1], 0.f);
                const long base = row_img * DIM + p * 64 + nn;
                *(float2*)&g_emb1[base] = o;
                const __nv_bfloat16 h0 = __float2bfloat16(o.x);
                const __nv_bfloat16 h1 = __float2bfloat16(o.y);
                __nv_bfloat162 hh; hh.x = h0; hh.y = h1;
                __nv_bfloat162 ll;
                ll.x = __float2bfloat16(o.x - __bfloat162float(h0));
                ll.y = __float2bfloat16(o.y - __bfloat162float(h1));
                *(__nv_bfloat162*)&g_emb1h[base] = hh;
                *(__nv_bfloat162*)&g_emb1l[base] = ll;
            }
        }
    }
}

// ---------------------------------------------------------------------------
// Tensor-core attention (as R6)
// ---------------------------------------------------------------------------
#define ATT_SMEM 94720

__global__ __launch_bounds__(256) void att_mma_kernel(
    int lvl, const float* __restrict__ b, const float* __restrict__ v,
    const float* __restrict__ vb)
{
    extern __shared__ char sm[];
    const unsigned sb32 = (unsigned)__cvta_generic_to_shared(sm);
    const int tid = threadIdx.x;
    const int row0 = blockIdx.x * 64;

    const __nv_bfloat16* eh = lvl == 0 ? g_emb1h : (lvl == 1 ? g_emb2h : g_emb3h);
    const __nv_bfloat16* el = lvl == 0 ? g_emb1l : (lvl == 1 ? g_emb2l : g_emb3l);
    const __nv_bfloat16* wh = g_awt_hi + (size_t)lvl * (NATT * DIM);
    const __nv_bfloat16* wl = g_awt_lo + (size_t)lvl * (NATT * DIM);
    float* s_out = s_buf(lvl);

    float* sbf  = (float*)(sm + 92160);
    float* svf  = (float*)(sm + 93184);
    float* wred = (float*)(sm + 94208);
    sbf[tid] = b[tid];
    svf[tid] = v[tid];

    const int l  = tid & 31, w = tid >> 5;
    const int mt = w & 3, nh = w >> 2;
    const int lane_r = ((l >> 3) & 1) * 8 + (l & 7);
    const unsigned khalf = ((l >> 4) & 1) * 16;

    float acc[16][4];
    #pragma unroll
    for (int j = 0; j < 16; j++)
        #pragma unroll
        for (int q = 0; q < 4; q++) acc[j][q] = 0.f;

    for (int kc = 0; kc < 16; kc++) {
        __syncthreads();
        const int k0 = kc * 64;
        for (int i = tid; i < 1024; i += 256) {
            const int pl = i >> 9, ii = i & 511;
            const int r = ii >> 3, c = ii & 7;
            const __nv_bfloat16* src =
                (pl ? el : eh) + (size_t)(row0 + r) * DIM + k0 + c * 8;
            *(uint4*)(sm + pl * 9216 + r * 144 + c * 16) = *(const uint4*)src;
        }
        for (int i = tid; i < 4096; i += 256) {
            const int pl = i >> 11, ii = i & 2047;
            const int n = ii >> 3, c = ii & 7;
            const __nv_bfloat16* src =
                (pl ? wl : wh) + (size_t)n * DIM + k0 + c * 8;
            *(uint4*)(sm + 18432 + pl * 36864 + n * 144 + c * 16) = *(const uint4*)src;
        }
        __syncthreads();

        #pragma unroll
        for (int ks = 0; ks < 4; ks++) {
            const unsigned aoff = (unsigned)(mt * 16 + lane_r) * 144 + ks * 32 + khalf;
            unsigned ah0, ah1, ah2, ah3, al0, al1, al2, al3;
            ldsm4(ah0, ah1, ah2, ah3, sb32 + aoff);
            ldsm4(al0, al1, al2, al3, sb32 + 9216 + aoff);
            #pragma unroll
            for (int g = 0; g < 4; g++) {
                const unsigned boff = (unsigned)(nh * 128 + g * 32 + l) * 144 + ks * 32;
                unsigned b0h[4], b1h[4], b0l[4], b1l[4];
                ldsm4(b0h[0], b0h[1], b0h[2], b0h[3], sb32 + 18432 + boff);
                ldsm4(b1h[0], b1h[1], b1h[2], b1h[3], sb32 + 18432 + boff + 16);
                ldsm4(b0l[0], b0l[1], b0l[2], b0l[3], sb32 + 55296 + boff);
                ldsm4(b1l[0], b1l[1], b1l[2], b1l[3], sb32 + 55296 + boff + 16);
                #pragma unroll
                for (int jj = 0; jj < 4; jj++) {
                    float* c = acc[g * 4 + jj];
                    mma_bf16(c, ah0, ah1, ah2, ah3, b0h[jj], b1h[jj]);
                    mma_bf16(c, ah0, ah1, ah2, ah3, b0l[jj], b1l[jj]);
                    mma_bf16(c, al0, al1, al2, al3, b0h[jj], b1h[jj]);
                }
            }
        }
    }

    float pvA = 0.f, pvB = 0.f;
    #pragma unroll
    for (int j = 0; j < 16; j++) {
        const int n = nh * 128 + j * 8 + (l & 3) * 2;
        const float b0v = sbf[n], b1v = sbf[n + 1];
        const float v0 = svf[n], v1 = svf[n + 1];
        pvA += tanhf(acc[j][0] + b0v) * v0 + tanhf(acc[j][1] + b1v) * v1;
        pvB += tanhf(acc[j][2] + b0v) * v0 + tanhf(acc[j][3] + b1v) * v1;
    }
    pvA += __shfl_xor_sync(0xffffffffu, pvA, 1);
    pvA += __shfl_xor_sync(0xffffffffu, pvA, 2);
    pvB += __shfl_xor_sync(0xffffffffu, pvB, 1);
    pvB += __shfl_xor_sync(0xffffffffu, pvB, 2);
    if ((l & 3) == 0) {
        const int r = l >> 2;
        wred[(mt * 16 + r) * 2 + nh]     = pvA;
        wred[(mt * 16 + r + 8) * 2 + nh] = pvB;
    }
    __syncthreads();
    if (tid < 64) {
        const float z = wred[tid * 2] + wred[tid * 2 + 1] + vb[0];
        s_out[row0 + tid] = 1.f / (1.f + expf(-z));
    }
}

// ---------------------------------------------------------------------------
__global__ __launch_bounds__(1024) void stats_kernel(int lvl, int R)
{
    __shared__ float red[1024];
    const float* s = s_buf(lvl);
    const int tid = threadIdx.x;

    float m = -1e30f;
    for (int i = tid; i < R; i += 1024) m = fmaxf(m, s[i]);
    red[tid] = m; __syncthreads();
    for (int off = 512; off; off >>= 1) {
        if (tid < off) red[tid] = fmaxf(red[tid], red[tid + off]);
        __syncthreads();
    }
    const float mx = red[0];
    __syncthreads();

    float sum = 0.f;
    for (int i = tid; i < R; i += 1024) sum += expf(s[i] - mx);
    red[tid] = sum; __syncthreads();
    for (int off = 512; off; off >>= 1) {
        if (tid < off) red[tid] += red[tid + off];
        __syncthreads();
    }
    if (tid == 0) { g_stats[lvl * 2] = mx; g_stats[lvl * 2 + 1] = red[0]; }
}

// ---------------------------------------------------------------------------
__global__ __launch_bounds__(256) void segsum_kernel(int lvl)
{
    __shared__ float ws[16];
    const float* ein  = emb_buf(lvl);
    float*       eout = emb_buf(lvl + 1);
    __nv_bfloat16* eouth = lvl == 0 ? g_emb2h : g_emb3h;
    __nv_bfloat16* eoutl = lvl == 0 ? g_emb2l : g_emb3l;
    const float* s    = s_buf(lvl);
    const int bg = blockIdx.x, tid = threadIdx.x;

    if (tid < 16) {
        const float mx = g_stats[lvl * 2];
        const float inv = 1.f / g_stats[lvl * 2 + 1];
        ws[tid] = expf(s[bg * 16 + tid] - mx) * inv;
    }
    __syncthreads();

    const float4* base = (const float4*)(ein + (long)bg * 16 * DIM);
    float4* dst = (float4*)(eout + (long)bg * DIM);
    for (int d = tid; d < DIM / 4; d += 256) {
        float4 a = make_float4(0.f, 0.f, 0.f, 0.f);
        #pragma unroll
        for (int i = 0; i < 16; i++) {
            const float w = ws[i];
            const float4 e = base[i * (DIM / 4) + d];
            a.x += w * e.x; a.y += w * e.y; a.z += w * e.z; a.w += w * e.w;
        }
        dst[d] = a;
        const long eb = (long)bg * DIM + d * 4;
        float av[4] = {a.x, a.y, a.z, a.w};
        #pragma unroll
        for (int q = 0; q < 4; q++) {
            const __nv_bfloat16 h = __float2bfloat16(av[q]);
            eouth[eb + q] = h;
            eoutl[eb + q] = __float2bfloat16(av[q] - __bfloat162float(h));
        }
    }
}

// ---------------------------------------------------------------------------
__global__ __launch_bounds__(512) void final_kernel(
    const float* __restrict__ clsW, const float* __restrict__ clsb,
    const float* __restrict__ outW, const float* __restrict__ outb,
    float* __restrict__ out)
{
    __shared__ float w3[64];
    __shared__ float outer[DIM];
    __shared__ float red[512];
    const int tid = threadIdx.x;
    const float* s3 = s_buf(2);

    if (tid == 0) {
        float mx = -1e30f;
        for (int i = 0; i < 64; i++) mx = fmaxf(mx, s3[i]);
        float sum = 0.f;
        for (int i = 0; i < 64; i++) { float e = expf(s3[i] - mx); w3[i] = e; sum += e; }
        const float inv = 1.f / sum;
        for (int i = 0; i < 64; i++) w3[i] *= inv;
    }
    __syncthreads();

    for (int d = tid; d < DIM; d += 512) {
        float acc = 0.f;
        #pragma unroll 8
        for (int b2 = 0; b2 < 64; b2++) acc += w3[b2] * g_emb3[b2 * DIM + d];
        outer[d] = acc;
    }
    __syncthreads();

    float acc = 0.f;
    const float* wp = clsW + tid;
    for (int d = 0; d < DIM; d++) acc += outer[d] * wp[d * NCLS];
    red[tid] = (acc + clsb[tid]) * outW[tid];
    __syncthreads();
    for (int off = 256; off; off >>= 1) {
        if (tid < off) red[tid] += red[tid + off];
        __syncthreads();
    }
    if (tid == 0) out[0] = 1.f / (1.f + expf(-(red[0] + outb[0])));
}

// ---------------------------------------------------------------------------
extern "C" void kernel_launch(void* const* d_in, const int* in_sizes, int n_in,
                              void* d_out, int out_size)
{
    const float* x    = (const float*)d_in[0];
    const float* c1w  = (const float*)d_in[1];
    const float* c1b  = (const float*)d_in[2];
    const float* c2w  = (const float*)d_in[3];
    const float* c2b  = (const float*)d_in[4];
    const float* a1W  = (const float*)d_in[5];
    const float* a1b  = (const float*)d_in[6];
    const float* a1v  = (const float*)d_in[7];
    const float* a1vb = (const float*)d_in[8];
    const float* a2W  = (const float*)d_in[9];
    const float* a2b  = (const float*)d_in[10];
    const float* a2v  = (const float*)d_in[11];
    const float* a2vb = (const float*)d_in[12];
    const float* a3W  = (const float*)d_in[13];
    const float* a3b  = (const float*)d_in[14];
    const float* a3v  = (const float*)d_in[15];
    const float* a3vb = (const float*)d_in[16];
    const float* clsW = (const float*)d_in[17];
    const float* clsb = (const float*)d_in[18];
    const float* outW = (const float*)d_in[19];
    const float* outb = (const float*)d_in[20];

    cudaFuncSetAttribute(fused_conv_kernel,
                         cudaFuncAttributeMaxDynamicSharedMemorySize, FC_SMEM);
    cudaFuncSetAttribute(att_mma_kernel,
                         cudaFuncAttributeMaxDynamicSharedMemorySize, ATT_SMEM);

    prep_w2t<<<200, 256>>>(c2w);
    prep_awt<<<1024, 256>>>(a1W, 0);
    prep_awt<<<1024, 256>>>(a2W, 1);
    prep_awt<<<1024, 256>>>(a3W, 2);

    fused_conv_kernel<<<N_INST, 256, FC_SMEM>>>(x, c1w, c1b, c2b);

    att_mma_kernel<<<N_INST / 64, 256, ATT_SMEM>>>(0, a1b, a1v, a1vb);
    stats_kernel<<<1, 1024>>>(0, N_INST);
    segsum_kernel<<<NB1, 256>>>(0);

    att_mma_kernel<<<NB1 / 64, 256, ATT_SMEM>>>(1, a2b, a2v, a2vb);
    stats_kernel<<<1, 1024>>>(1, NB1);
    segsum_kernel<<<NB2, 256>>>(1);

    att_mma_kernel<<<NB2 / 64, 256, ATT_SMEM>>>(2, a3b, a3v, a3vb);
    final_kernel<<<1, 512>>>(clsW, clsb, outW, outb, (float*)d_out);
}

// round 8
// speedup vs baseline: 1.2729x; 1.2729x over previous
#include <cuda_runtime.h>
#include <cuda_bf16.h>
#include <math.h>

#define N_INST 16384
#define NB1    1024
#define NB2    64
#define DIM    1024
#define NATT   256
#define NCLS   512

// ---------------- scratch (device globals; no allocation allowed) ----------
__device__ float g_emb1[N_INST * DIM];   // 64 MB
__device__ float g_emb2[NB1 * DIM];
__device__ float g_emb3[NB2 * DIM];
__device__ float g_s[N_INST + NB1 + NB2];
__device__ float g_stats[8];
// conv2 weights, transposed [n=64][k=800], split into bf16 hi/lo
__device__ __nv_bfloat16 g_w2t_hi[64 * 800];
__device__ __nv_bfloat16 g_w2t_lo[64 * 800];
// embeddings as bf16 hi/lo (for tensor-core attention GEMMs)
__device__ __nv_bfloat16 g_emb1h[N_INST * DIM], g_emb1l[N_INST * DIM];
__device__ __nv_bfloat16 g_emb2h[NB1 * DIM],    g_emb2l[NB1 * DIM];
__device__ __nv_bfloat16 g_emb3h[NB2 * DIM],    g_emb3l[NB2 * DIM];
// attention weights, transposed [n=256][k=1024], hi/lo, 3 levels
__device__ __nv_bfloat16 g_awt_hi[3 * NATT * DIM];
__device__ __nv_bfloat16 g_awt_lo[3 * NATT * DIM];

__device__ __forceinline__ float* emb_buf(int lvl) {
    return lvl == 0 ? g_emb1 : (lvl == 1 ? g_emb2 : g_emb3);
}
__device__ __forceinline__ float* s_buf(int lvl) {
    return lvl == 0 ? g_s : (lvl == 1 ? g_s + N_INST : g_s + N_INST + NB1);
}

// ---------------- mma helpers ----------------------------------------------
__device__ __forceinline__ void ldsm4(unsigned& r0, unsigned& r1, unsigned& r2,
                                      unsigned& r3, unsigned a) {
    asm volatile("ldmatrix.sync.aligned.m8n8.x4.shared.b16 {%0,%1,%2,%3}, [%4];"
                 : "=r"(r0), "=r"(r1), "=r"(r2), "=r"(r3) : "r"(a));
}
__device__ __forceinline__ void mma_bf16(float* c, unsigned a0, unsigned a1,
                                         unsigned a2, unsigned a3,
                                         unsigned b0, unsigned b1) {
    asm volatile(
        "mma.sync.aligned.m16n8k16.row.col.f32.bf16.bf16.f32 "
        "{%0,%1,%2,%3},{%4,%5,%6,%7},{%8,%9},{%0,%1,%2,%3};"
        : "+f"(c[0]), "+f"(c[1]), "+f"(c[2]), "+f"(c[3])
        : "r"(a0), "r"(a1), "r"(a2), "r"(a3), "r"(b0), "r"(b1));
}

// ---------------------------------------------------------------------------
// Prep kernels: weight transposes + bf16 hi/lo splits
// ---------------------------------------------------------------------------
__global__ __launch_bounds__(256) void prep_w2t(const float* __restrict__ w2) {
    const int idx = blockIdx.x * 256 + threadIdx.x;
    if (idx >= 64 * 800) return;
    const int n = idx / 800, k = idx - n * 800;
    const float v = w2[k * 64 + n];
    const __nv_bfloat16 h = __float2bfloat16(v);
    g_w2t_hi[idx] = h;
    g_w2t_lo[idx] = __float2bfloat16(v - __bfloat162float(h));
}

__global__ __launch_bounds__(256) void prep_awt_all(
    const float* __restrict__ W0, const float* __restrict__ W1,
    const float* __restrict__ W2)
{
    const int gidx = blockIdx.x * 256 + threadIdx.x;   // 3*262144
    const int set = gidx >> 18;
    const int idx = gidx & 262143;
    const float* W = set == 0 ? W0 : (set == 1 ? W1 : W2);
    const int n = idx >> 10, k = idx & 1023;
    const float v = W[k * NATT + n];
    const __nv_bfloat16 h = __float2bfloat16(v);
    g_awt_hi[set * (NATT * DIM) + idx] = h;
    g_awt_lo[set * (NATT * DIM) + idx] = __float2bfloat16(v - __bfloat162float(h));
}

// ---------------------------------------------------------------------------
// Fused conv kernel: one CTA = 2 images (R6 structure; Phase B m32n32 warps)
// ---------------------------------------------------------------------------
#define FC_SMEM 89088

__global__ __launch_bounds__(256) void fused_conv_kernel(
    const float* __restrict__ x,
    const float* __restrict__ w1, const float* __restrict__ b1,
    const float* __restrict__ b2)
{
    extern __shared__ char smem[];
    const unsigned sbase = (unsigned)__cvta_generic_to_shared(smem);
    const int tid = threadIdx.x;

    __nv_bfloat16* p1h = (__nv_bfloat16*)smem;             // [img][144*40]
    __nv_bfloat16* p1l = (__nv_bfloat16*)(smem + 23040);

    // ---------------- Phase A: conv1 + relu + pool (scalar fp32) ----------
    {
        float* stg  = (float*)(smem + 46080);
        float* w1_s = stg;          // 800
        float* b1_s = stg + 800;    // 32
        float* in_s = stg + 832;    // 2 x 784
        for (int i = tid; i < 800; i += 256) w1_s[i] = w1[i];
        if (tid < 32) b1_s[tid] = b1[tid];
        const float* x0 = x + (size_t)blockIdx.x * 2 * 784;
        for (int i = tid; i < 1568; i += 256) in_s[i] = x0[i];
        __syncthreads();

        for (int t = tid; t < 2304; t += 256) {
            const int img = t >= 1152;
            const int tt  = t - img * 1152;
            const float* in = in_s + img * 784;
            const int c0 = (tt & 7) * 4;
            const int p  = tt >> 3;
            const int pr = p / 12, pc = p % 12;
            const int y0 = pr * 2, xx0 = pc * 2;
            float acc[4][4];
            #pragma unroll
            for (int j = 0; j < 4; j++)
                #pragma unroll
                for (int ch = 0; ch < 4; ch++) acc[j][ch] = 0.f;

            for (int ky = 0; ky < 5; ky++) {
                #pragma unroll
                for (int kx = 0; kx < 5; kx++) {
                    const float4 wv = *(const float4*)&w1_s[(ky * 5 + kx) * 32 + c0];
                    #pragma unroll
                    for (int j = 0; j < 4; j++) {
                        const int dy = j >> 1, dx = j & 1;
                        const float iv = in[(y0 + dy + ky) * 28 + (xx0 + dx + kx)];
                        acc[j][0] += iv * wv.x; acc[j][1] += iv * wv.y;
                        acc[j][2] += iv * wv.z; acc[j][3] += iv * wv.w;
                    }
                }
            }
            __nv_bfloat16* ph = p1h + img * 5760 + p * 40 + c0;
            __nv_bfloat16* pl = p1l + img * 5760 + p * 40 + c0;
            #pragma unroll
            for (int ch = 0; ch < 4; ch++) {
                float m = fmaxf(fmaxf(acc[0][ch], acc[1][ch]),
                                fmaxf(acc[2][ch], acc[3][ch]));
                const float v = fmaxf(m + b1_s[c0 + ch], 0.f);
                const __nv_bfloat16 h = __float2bfloat16(v);
                ph[ch] = h;
                pl[ch] = __float2bfloat16(v - __bfloat162float(h));
            }
        }
    }

    // ---------------- Phase B: conv2 via bf16 tensor-core GEMM ------------
    // 8 warps = 2 img x 2 m-pairs x 2 n-halves; each warp m32 x n32.
    {
        const int l   = tid & 31;
        const int w   = tid >> 5;
        const int img = w >> 2;          // image within CTA
        const int mp  = (w >> 1) & 1;    // m-pair (rows 0-31 / 32-63)
        const int nh  = w & 1;           // n half (0-31 / 32-63)

        const int lane_r = ((l >> 3) & 1) * 8 + (l & 7);
        const unsigned khalf = ((l >> 4) & 1) * 16;

        unsigned abase[2];
        #pragma unroll
        for (int s = 0; s < 2; s++) {
            const int pos = (mp * 2 + s) * 16 + lane_r;
            abase[s] = (unsigned)(((pos >> 3) * 12 + (pos & 7)) * 80);
        }

        const unsigned aHb = sbase + img * 11520;
        const unsigned aLb = sbase + 23040 + img * 11520;
        const unsigned BHb = sbase + 46080;
        const unsigned BLb = BHb + 21504;

        float acc[2][4][4];
        #pragma unroll
        for (int s = 0; s < 2; s++)
            #pragma unroll
            for (int j = 0; j < 4; j++)
                #pragma unroll
                for (int q = 0; q < 4; q++) acc[s][j][q] = 0.f;

        const char* wth = (const char*)g_w2t_hi;
        const char* wtl = (const char*)g_w2t_lo;

        for (int ky = 0; ky < 5; ky++) {
            __syncthreads();   // previous slab (or phase-A staging) consumed
            for (int i = tid; i < 2560; i += 256) {
                const int s  = i >= 1280;
                const int ii = i - s * 1280;
                const int n  = ii / 20, c = ii - n * 20;
                const char* src = (s ? wtl : wth) + n * 1600 + ky * 320 + c * 16;
                char* dst = smem + 46080 + s * 21504 + n * 336 + c * 16;
                *(uint4*)dst = *(const uint4*)src;
            }
            __syncthreads();

            const unsigned kyoff = (unsigned)ky * 960;
            for (int kx = 0; kx < 5; kx++) {
                #pragma unroll
                for (int hf = 0; hf < 2; hf++) {
                    // B fragments: load once, reuse for both m-tiles
                    const unsigned kb = (unsigned)(kx * 2 + hf) * 32;
                    const unsigned brow = (unsigned)(nh * 32 + l) * 336 + kb;
                    unsigned bh[8], bl[8];
                    ldsm4(bh[0], bh[1], bh[2], bh[3], BHb + brow);
                    ldsm4(bh[4], bh[5], bh[6], bh[7], BHb + brow + 16);
                    ldsm4(bl[0], bl[1], bl[2], bl[3], BLb + brow);
                    ldsm4(bl[4], bl[5], bl[6], bl[7], BLb + brow + 16);

                    #pragma unroll
                    for (int s = 0; s < 2; s++) {
                        const unsigned ab =
                            abase[s] + kyoff + kx * 80 + khalf + hf * 32;
                        unsigned ah0, ah1, ah2, ah3, al0, al1, al2, al3;
                        ldsm4(ah0, ah1, ah2, ah3, aHb + ab);
                        ldsm4(al0, al1, al2, al3, aLb + ab);
                        #pragma unroll
                        for (int j = 0; j < 4; j++) {
                            mma_bf16(acc[s][j], ah0, ah1, ah2, ah3, bh[j], bh[4 + j]);
                            mma_bf16(acc[s][j], ah0, ah1, ah2, ah3, bl[j], bl[4 + j]);
                            mma_bf16(acc[s][j], al0, al1, al2, al3, bh[j], bh[4 + j]);
                        }
                    }
                }
            }
        }

        // epilogue: 2x2 maxpool + bias + relu -> emb1 (fp32 + bf16 hi/lo)
        const long row_img = (long)blockIdx.x * 2 + img;
        #pragma unroll
        for (int s = 0; s < 2; s++) {
            const int mt = mp * 2 + s;
            #pragma unroll
            for (int j = 0; j < 4; j++) {
                float v0 = fmaxf(acc[s][j][0], acc[s][j][2]);
                float v1 = fmaxf(acc[s][j][1], acc[s][j][3]);
                const float u0 = fmaxf(v0, __shfl_down_sync(0xffffffffu, v0, 4));
                const float u1 = fmaxf(v1, __shfl_down_sync(0xffffffffu, v1, 4));
                if (((l >> 2) & 1) == 0) {
                    const int pc = l >> 3;
                    const int p  = mt * 4 + pc;
                    const int nn = nh * 32 + j * 8 + 2 * (l & 3);
                    float2 o;
                    o.x = fmaxf(u0 + b2[nn], 0.f);
                    o.y = fmaxf(u1 + b2[nn + 1], 0.f);
                    const long base = row_img * DIM + p * 64 + nn;
                    *(float2*)&g_emb1[base] = o;
                    const __nv_bfloat16 h0 = __float2bfloat16(o.x);
                    const __nv_bfloat16 h1 = __float2bfloat16(o.y);
                    __nv_bfloat162 hh; hh.x = h0; hh.y = h1;
                    __nv_bfloat162 ll;
                    ll.x = __float2bfloat16(o.x - __bfloat162float(h0));
                    ll.y = __float2bfloat16(o.y - __bfloat162float(h1));
                    *(__nv_bfloat162*)&g_emb1h[base] = hh;
                    *(__nv_bfloat162*)&g_emb1l[base] = ll;
                }
            }
        }
    }
}

// ---------------------------------------------------------------------------
// Tensor-core attention (as R6)
// ---------------------------------------------------------------------------
#define ATT_SMEM 94720

__global__ __launch_bounds__(256) void att_mma_kernel(
    int lvl, const float* __restrict__ b, const float* __restrict__ v,
    const float* __restrict__ vb)
{
    extern __shared__ char sm[];
    const unsigned sb32 = (unsigned)__cvta_generic_to_shared(sm);
    const int tid = threadIdx.x;
    const int row0 = blockIdx.x * 64;

    const __nv_bfloat16* eh = lvl == 0 ? g_emb1h : (lvl == 1 ? g_emb2h : g_emb3h);
    const __nv_bfloat16* el = lvl == 0 ? g_emb1l : (lvl == 1 ? g_emb2l : g_emb3l);
    const __nv_bfloat16* wh = g_awt_hi + (size_t)lvl * (NATT * DIM);
    const __nv_bfloat16* wl = g_awt_lo + (size_t)lvl * (NATT * DIM);
    float* s_out = s_buf(lvl);

    float* sbf  = (float*)(sm + 92160);
    float* svf  = (float*)(sm + 93184);
    float* wred = (float*)(sm + 94208);
    sbf[tid] = b[tid];
    svf[tid] = v[tid];

    const int l  = tid & 31, w = tid >> 5;
    const int mt = w & 3, nh = w >> 2;
    const int lane_r = ((l >> 3) & 1) * 8 + (l & 7);
    const unsigned khalf = ((l >> 4) & 1) * 16;

    float acc[16][4];
    #pragma unroll
    for (int j = 0; j < 16; j++)
        #pragma unroll
        for (int q = 0; q < 4; q++) acc[j][q] = 0.f;

    for (int kc = 0; kc < 16; kc++) {
        __syncthreads();
        const int k0 = kc * 64;
        for (int i = tid; i < 1024; i += 256) {
            const int pl = i >> 9, ii = i & 511;
            const int r = ii >> 3, c = ii & 7;
            const __nv_bfloat16* src =
                (pl ? el : eh) + (size_t)(row0 + r) * DIM + k0 + c * 8;
            *(uint4*)(sm + pl * 9216 + r * 144 + c * 16) = *(const uint4*)src;
        }
        for (int i = tid; i < 4096; i += 256) {
            const int pl = i >> 11, ii = i & 2047;
            const int n = ii >> 3, c = ii & 7;
            const __nv_bfloat16* src =
                (pl ? wl : wh) + (size_t)n * DIM + k0 + c * 8;
            *(uint4*)(sm + 18432 + pl * 36864 + n * 144 + c * 16) = *(const uint4*)src;
        }
        __syncthreads();

        #pragma unroll
        for (int ks = 0; ks < 4; ks++) {
            const unsigned aoff = (unsigned)(mt * 16 + lane_r) * 144 + ks * 32 + khalf;
            unsigned ah0, ah1, ah2, ah3, al0, al1, al2, al3;
            ldsm4(ah0, ah1, ah2, ah3, sb32 + aoff);
            ldsm4(al0, al1, al2, al3, sb32 + 9216 + aoff);
            #pragma unroll
            for (int g = 0; g < 4; g++) {
                const unsigned boff = (unsigned)(nh * 128 + g * 32 + l) * 144 + ks * 32;
                unsigned b0h[4], b1h[4], b0l[4], b1l[4];
                ldsm4(b0h[0], b0h[1], b0h[2], b0h[3], sb32 + 18432 + boff);
                ldsm4(b1h[0], b1h[1], b1h[2], b1h[3], sb32 + 18432 + boff + 16);
                ldsm4(b0l[0], b0l[1], b0l[2], b0l[3], sb32 + 55296 + boff);
                ldsm4(b1l[0], b1l[1], b1l[2], b1l[3], sb32 + 55296 + boff + 16);
                #pragma unroll
                for (int jj = 0; jj < 4; jj++) {
                    float* c = acc[g * 4 + jj];
                    mma_bf16(c, ah0, ah1, ah2, ah3, b0h[jj], b1h[jj]);
                    mma_bf16(c, ah0, ah1, ah2, ah3, b0l[jj], b1l[jj]);
                    mma_bf16(c, al0, al1, al2, al3, b0h[jj], b1h[jj]);
                }
            }
        }
    }

    float pvA = 0.f, pvB = 0.f;
    #pragma unroll
    for (int j = 0; j < 16; j++) {
        const int n = nh * 128 + j * 8 + (l & 3) * 2;
        const float b0v = sbf[n], b1v = sbf[n + 1];
        const float v0 = svf[n], v1 = svf[n + 1];
        pvA += tanhf(acc[j][0] + b0v) * v0 + tanhf(acc[j][1] + b1v) * v1;
        pvB += tanhf(acc[j][2] + b0v) * v0 + tanhf(acc[j][3] + b1v) * v1;
    }
    pvA += __shfl_xor_sync(0xffffffffu, pvA, 1);
    pvA += __shfl_xor_sync(0xffffffffu, pvA, 2);
    pvB += __shfl_xor_sync(0xffffffffu, pvB, 1);
    pvB += __shfl_xor_sync(0xffffffffu, pvB, 2);
    if ((l & 3) == 0) {
        const int r = l >> 2;
        wred[(mt * 16 + r) * 2 + nh]     = pvA;
        wred[(mt * 16 + r + 8) * 2 + nh] = pvB;
    }
    __syncthreads();
    if (tid < 64) {
        const float z = wred[tid * 2] + wred[tid * 2 + 1] + vb[0];
        s_out[row0 + tid] = 1.f / (1.f + expf(-z));
    }
}

// ---------------------------------------------------------------------------
__global__ __launch_bounds__(1024) void stats_kernel(int lvl, int R)
{
    __shared__ float red[1024];
    const float* s = s_buf(lvl);
    const int tid = threadIdx.x;

    float m = -1e30f;
    for (int i = tid; i < R; i += 1024) m = fmaxf(m, s[i]);
    red[tid] = m; __syncthreads();
    for (int off = 512; off; off >>= 1) {
        if (tid < off) red[tid] = fmaxf(red[tid], red[tid + off]);
        __syncthreads();
    }
    const float mx = red[0];
    __syncthreads();

    float sum = 0.f;
    for (int i = tid; i < R; i += 1024) sum += expf(s[i] - mx);
    red[tid] = sum; __syncthreads();
    for (int off = 512; off; off >>= 1) {
        if (tid < off) red[tid] += red[tid + off];
        __syncthreads();
    }
    if (tid == 0) { g_stats[lvl * 2] = mx; g_stats[lvl * 2 + 1] = red[0]; }
}

// ---------------------------------------------------------------------------
__global__ __launch_bounds__(256) void segsum_kernel(int lvl)
{
    __shared__ float ws[16];
    const float* ein  = emb_buf(lvl);
    float*       eout = emb_buf(lvl + 1);
    __nv_bfloat16* eouth = lvl == 0 ? g_emb2h : g_emb3h;
    __nv_bfloat16* eoutl = lvl == 0 ? g_emb2l : g_emb3l;
    const float* s    = s_buf(lvl);
    const int bg = blockIdx.x, tid = threadIdx.x;

    if (tid < 16) {
        const float mx = g_stats[lvl * 2];
        const float inv = 1.f / g_stats[lvl * 2 + 1];
        ws[tid] = expf(s[bg * 16 + tid] - mx) * inv;
    }
    __syncthreads();

    const float4* base = (const float4*)(ein + (long)bg * 16 * DIM);
    float4* dst = (float4*)(eout + (long)bg * DIM);
    for (int d = tid; d < DIM / 4; d += 256) {
        float4 a = make_float4(0.f, 0.f, 0.f, 0.f);
        #pragma unroll
        for (int i = 0; i < 16; i++) {
            const float w = ws[i];
            const float4 e = base[i * (DIM / 4) + d];
            a.x += w * e.x; a.y += w * e.y; a.z += w * e.z; a.w += w * e.w;
        }
        dst[d] = a;
        const long eb = (long)bg * DIM + d * 4;
        float av[4] = {a.x, a.y, a.z, a.w};
        #pragma unroll
        for (int q = 0; q < 4; q++) {
            const __nv_bfloat16 h = __float2bfloat16(av[q]);
            eouth[eb + q] = h;
            eoutl[eb + q] = __float2bfloat16(av[q] - __bfloat162float(h));
        }
    }
}

// ---------------------------------------------------------------------------
__global__ __launch_bounds__(512) void final_kernel(
    const float* __restrict__ clsW, const float* __restrict__ clsb,
    const float* __restrict__ outW, const float* __restrict__ outb,
    float* __restrict__ out)
{
    __shared__ float w3[64];
    __shared__ float outer[DIM];
    __shared__ float red[512];
    const int tid = threadIdx.x;
    const float* s3 = s_buf(2);

    if (tid == 0) {
        float mx = -1e30f;
        for (int i = 0; i < 64; i++) mx = fmaxf(mx, s3[i]);
        float sum = 0.f;
        for (int i = 0; i < 64; i++) { float e = expf(s3[i] - mx); w3[i] = e; sum += e; }
        const float inv = 1.f / sum;
        for (int i = 0; i < 64; i++) w3[i] *= inv;
    }
    __syncthreads();

    for (int d = tid; d < DIM; d += 512) {
        float acc = 0.f;
        #pragma unroll 8
        for (int b2 = 0; b2 < 64; b2++) acc += w3[b2] * g_emb3[b2 * DIM + d];
        outer[d] = acc;
    }
    __syncthreads();

    float acc = 0.f;
    const float* wp = clsW + tid;
    for (int d = 0; d < DIM; d++) acc += outer[d] * wp[d * NCLS];
    red[tid] = (acc + clsb[tid]) * outW[tid];
    __syncthreads();
    for (int off = 256; off; off >>= 1) {
        if (tid < off) red[tid] += red[tid + off];
        __syncthreads();
    }
    if (tid == 0) out[0] = 1.f / (1.f + expf(-(red[0] + outb[0])));
}

// ---------------------------------------------------------------------------
extern "C" void kernel_launch(void* const* d_in, const int* in_sizes, int n_in,
                              void* d_out, int out_size)
{
    const float* x    = (const float*)d_in[0];
    const float* c1w  = (const float*)d_in[1];
    const float* c1b  = (const float*)d_in[2];
    const float* c2w  = (const float*)d_in[3];
    const float* c2b  = (const float*)d_in[4];
    const float* a1W  = (const float*)d_in[5];
    const float* a1b  = (const float*)d_in[6];
    const float* a1v  = (const float*)d_in[7];
    const float* a1vb = (const float*)d_in[8];
    const float* a2W  = (const float*)d_in[9];
    const float* a2b  = (const float*)d_in[10];
    const float* a2v  = (const float*)d_in[11];
    const float* a2vb = (const float*)d_in[12];
    const float* a3W  = (const float*)d_in[13];
    const float* a3b  = (const float*)d_in[14];
    const float* a3v  = (const float*)d_in[15];
    const float* a3vb = (const float*)d_in[16];
    const float* clsW = (const float*)d_in[17];
    const float* clsb = (const float*)d_in[18];
    const float* outW = (const float*)d_in[19];
    const float* outb = (const float*)d_in[20];

    cudaFuncSetAttribute(fused_conv_kernel,
                         cudaFuncAttributeMaxDynamicSharedMemorySize, FC_SMEM);
    cudaFuncSetAttribute(att_mma_kernel,
                         cudaFuncAttributeMaxDynamicSharedMemorySize, ATT_SMEM);

    prep_w2t<<<200, 256>>>(c2w);
    prep_awt_all<<<3072, 256>>>(a1W, a2W, a3W);

    fused_conv_kernel<<<N_INST / 2, 256, FC_SMEM>>>(x, c1w, c1b, c2b);

    att_mma_kernel<<<N_INST / 64, 256, ATT_SMEM>>>(0, a1b, a1v, a1vb);
    stats_kernel<<<1, 1024>>>(0, N_INST);
    segsum_kernel<<<NB1, 256>>>(0);

    att_mma_kernel<<<NB1 / 64, 256, ATT_SMEM>>>(1, a2b, a2v, a2vb);
    stats_kernel<<<1, 1024>>>(1, NB1);
    segsum_kernel<<<NB2, 256>>>(1);

    att_mma_kernel<<<NB2 / 64, 256, ATT_SMEM>>>(2, a3b, a3v, a3vb);
    final_kernel<<<1, 512>>>(clsW, clsb, outW, outb, (float*)d_out);
}

// round 9
// speedup vs baseline: 1.3458x; 1.0573x over previous
#include <cuda_runtime.h>
#include <cuda_bf16.h>
#include <math.h>

#define N_INST 16384
#define NB1    1024
#define NB2    64
#define DIM    1024
#define NATT   256
#define NCLS   512

// ---------------- scratch (device globals; no allocation allowed) ----------
__device__ float g_emb1[N_INST * DIM];   // 64 MB
__device__ float g_emb2[NB1 * DIM];
__device__ float g_emb3[NB2 * DIM];
__device__ float g_s[N_INST + NB1 + NB2];
__device__ float g_stats[8];
// conv2 weights, transposed [n=64][k=800], split into bf16 hi/lo
__device__ __nv_bfloat16 g_w2t_hi[64 * 800];
__device__ __nv_bfloat16 g_w2t_lo[64 * 800];
// embeddings as bf16 hi/lo (for tensor-core attention GEMMs)
__device__ __nv_bfloat16 g_emb1h[N_INST * DIM], g_emb1l[N_INST * DIM];
__device__ __nv_bfloat16 g_emb2h[NB1 * DIM],    g_emb2l[NB1 * DIM];
__device__ __nv_bfloat16 g_emb3h[NB2 * DIM],    g_emb3l[NB2 * DIM];
// attention weights, transposed [n=256][k=1024], hi/lo, 3 levels
__device__ __nv_bfloat16 g_awt_hi[3 * NATT * DIM];
__device__ __nv_bfloat16 g_awt_lo[3 * NATT * DIM];

__device__ __forceinline__ float* emb_buf(int lvl) {
    return lvl == 0 ? g_emb1 : (lvl == 1 ? g_emb2 : g_emb3);
}
__device__ __forceinline__ float* s_buf(int lvl) {
    return lvl == 0 ? g_s : (lvl == 1 ? g_s + N_INST : g_s + N_INST + NB1);
}

// ---------------- mma helpers ----------------------------------------------
__device__ __forceinline__ void ldsm4(unsigned& r0, unsigned& r1, unsigned& r2,
                                      unsigned& r3, unsigned a) {
    asm volatile("ldmatrix.sync.aligned.m8n8.x4.shared.b16 {%0,%1,%2,%3}, [%4];"
                 : "=r"(r0), "=r"(r1), "=r"(r2), "=r"(r3) : "r"(a));
}
__device__ __forceinline__ void mma_bf16(float* c, unsigned a0, unsigned a1,
                                         unsigned a2, unsigned a3,
                                         unsigned b0, unsigned b1) {
    asm volatile(
        "mma.sync.aligned.m16n8k16.row.col.f32.bf16.bf16.f32 "
        "{%0,%1,%2,%3},{%4,%5,%6,%7},{%8,%9},{%0,%1,%2,%3};"
        : "+f"(c[0]), "+f"(c[1]), "+f"(c[2]), "+f"(c[3])
        : "r"(a0), "r"(a1), "r"(a2), "r"(a3), "r"(b0), "r"(b1));
}

// ---------------------------------------------------------------------------
// Prep kernels: weight transposes + bf16 hi/lo splits
// ---------------------------------------------------------------------------
__global__ __launch_bounds__(256) void prep_w2t(const float* __restrict__ w2) {
    const int idx = blockIdx.x * 256 + threadIdx.x;
    if (idx >= 64 * 800) return;
    const int n = idx / 800, k = idx - n * 800;
    const float v = w2[k * 64 + n];
    const __nv_bfloat16 h = __float2bfloat16(v);
    g_w2t_hi[idx] = h;
    g_w2t_lo[idx] = __float2bfloat16(v - __bfloat162float(h));
}

__global__ __launch_bounds__(256) void prep_awt_all(
    const float* __restrict__ W0, const float* __restrict__ W1,
    const float* __restrict__ W2)
{
    const int gidx = blockIdx.x * 256 + threadIdx.x;   // 3*262144
    const int set = gidx >> 18;
    const int idx = gidx & 262143;
    const float* W = set == 0 ? W0 : (set == 1 ? W1 : W2);
    const int n = idx >> 10, k = idx & 1023;
    const float v = W[k * NATT + n];
    const __nv_bfloat16 h = __float2bfloat16(v);
    g_awt_hi[set * (NATT * DIM) + idx] = h;
    g_awt_lo[set * (NATT * DIM) + idx] = __float2bfloat16(v - __bfloat162float(h));
}

// ---------------------------------------------------------------------------
// Fused conv kernel: one CTA = 2 images; 2 CTAs/SM (latency hiding).
// ---------------------------------------------------------------------------
#define FC_SMEM 89088

__global__ __launch_bounds__(256, 2) void fused_conv_kernel(
    const float* __restrict__ x,
    const float* __restrict__ w1, const float* __restrict__ b1,
    const float* __restrict__ b2)
{
    extern __shared__ char smem[];
    const unsigned sbase = (unsigned)__cvta_generic_to_shared(smem);
    const int tid = threadIdx.x;

    __nv_bfloat16* p1h = (__nv_bfloat16*)smem;             // [img][144*40]
    __nv_bfloat16* p1l = (__nv_bfloat16*)(smem + 23040);

    // ---------------- Phase A: conv1 + relu + pool (scalar fp32) ----------
    {
        float* stg  = (float*)(smem + 46080);
        float* w1_s = stg;          // 800
        float* b1_s = stg + 800;    // 32
        float* in_s = stg + 832;    // 2 x 784
        for (int i = tid; i < 800; i += 256) w1_s[i] = w1[i];
        if (tid < 32) b1_s[tid] = b1[tid];
        const float* x0 = x + (size_t)blockIdx.x * 2 * 784;
        for (int i = tid; i < 1568; i += 256) in_s[i] = x0[i];
        __syncthreads();

        for (int t = tid; t < 2304; t += 256) {
            const int img = t >= 1152;
            const int tt  = t - img * 1152;
            const float* in = in_s + img * 784;
            const int c0 = (tt & 7) * 4;
            const int p  = tt >> 3;
            const int pr = p / 12, pc = p % 12;
            const int y0 = pr * 2, xx0 = pc * 2;
            float acc[4][4];
            #pragma unroll
            for (int j = 0; j < 4; j++)
                #pragma unroll
                for (int ch = 0; ch < 4; ch++) acc[j][ch] = 0.f;

            for (int ky = 0; ky < 5; ky++) {
                #pragma unroll
                for (int kx = 0; kx < 5; kx++) {
                    const float4 wv = *(const float4*)&w1_s[(ky * 5 + kx) * 32 + c0];
                    #pragma unroll
                    for (int j = 0; j < 4; j++) {
                        const int dy = j >> 1, dx = j & 1;
                        const float iv = in[(y0 + dy + ky) * 28 + (xx0 + dx + kx)];
                        acc[j][0] += iv * wv.x; acc[j][1] += iv * wv.y;
                        acc[j][2] += iv * wv.z; acc[j][3] += iv * wv.w;
                    }
                }
            }
            __nv_bfloat16* ph = p1h + img * 5760 + p * 40 + c0;
            __nv_bfloat16* pl = p1l + img * 5760 + p * 40 + c0;
            #pragma unroll
            for (int ch = 0; ch < 4; ch++) {
                float m = fmaxf(fmaxf(acc[0][ch], acc[1][ch]),
                                fmaxf(acc[2][ch], acc[3][ch]));
                const float v = fmaxf(m + b1_s[c0 + ch], 0.f);
                const __nv_bfloat16 h = __float2bfloat16(v);
                ph[ch] = h;
                pl[ch] = __float2bfloat16(v - __bfloat162float(h));
            }
        }
    }

    // ---------------- Phase B: conv2 via bf16 tensor-core GEMM ------------
    // 8 warps = 2 img x 2 m-pairs x 2 n-halves; each warp m32 x n32.
    {
        const int l   = tid & 31;
        const int w   = tid >> 5;
        const int img = w >> 2;
        const int mp  = (w >> 1) & 1;
        const int nh  = w & 1;

        const int lane_r = ((l >> 3) & 1) * 8 + (l & 7);
        const unsigned khalf = ((l >> 4) & 1) * 16;

        unsigned abase[2];
        #pragma unroll
        for (int s = 0; s < 2; s++) {
            const int pos = (mp * 2 + s) * 16 + lane_r;
            abase[s] = (unsigned)(((pos >> 3) * 12 + (pos & 7)) * 80);
        }

        const unsigned aHb = sbase + img * 11520;
        const unsigned aLb = sbase + 23040 + img * 11520;
        const unsigned BHb = sbase + 46080;
        const unsigned BLb = BHb + 21504;

        float acc[2][4][4];
        #pragma unroll
        for (int s = 0; s < 2; s++)
            #pragma unroll
            for (int j = 0; j < 4; j++)
                #pragma unroll
                for (int q = 0; q < 4; q++) acc[s][j][q] = 0.f;

        const char* wth = (const char*)g_w2t_hi;
        const char* wtl = (const char*)g_w2t_lo;

        for (int ky = 0; ky < 5; ky++) {
            __syncthreads();
            for (int i = tid; i < 2560; i += 256) {
                const int s  = i >= 1280;
                const int ii = i - s * 1280;
                const int n  = ii / 20, c = ii - n * 20;
                const char* src = (s ? wtl : wth) + n * 1600 + ky * 320 + c * 16;
                char* dst = smem + 46080 + s * 21504 + n * 336 + c * 16;
                *(uint4*)dst = *(const uint4*)src;
            }
            __syncthreads();

            const unsigned kyoff = (unsigned)ky * 960;
            for (int kx = 0; kx < 5; kx++) {
                #pragma unroll
                for (int hf = 0; hf < 2; hf++) {
                    const unsigned kb = (unsigned)(kx * 2 + hf) * 32;
                    const unsigned brow = (unsigned)(nh * 32 + l) * 336 + kb;
                    unsigned bh[8], bl[8];
                    ldsm4(bh[0], bh[1], bh[2], bh[3], BHb + brow);
                    ldsm4(bh[4], bh[5], bh[6], bh[7], BHb + brow + 16);
                    ldsm4(bl[0], bl[1], bl[2], bl[3], BLb + brow);
                    ldsm4(bl[4], bl[5], bl[6], bl[7], BLb + brow + 16);

                    #pragma unroll
                    for (int s = 0; s < 2; s++) {
                        const unsigned ab =
                            abase[s] + kyoff + kx * 80 + khalf + hf * 32;
                        unsigned ah0, ah1, ah2, ah3, al0, al1, al2, al3;
                        ldsm4(ah0, ah1, ah2, ah3, aHb + ab);
                        ldsm4(al0, al1, al2, al3, aLb + ab);
                        #pragma unroll
                        for (int j = 0; j < 4; j++) {
                            mma_bf16(acc[s][j], ah0, ah1, ah2, ah3, bh[j], bh[4 + j]);
                            mma_bf16(acc[s][j], ah0, ah1, ah2, ah3, bl[j], bl[4 + j]);
                            mma_bf16(acc[s][j], al0, al1, al2, al3, bh[j], bh[4 + j]);
                        }
                    }
                }
            }
        }

        // epilogue: 2x2 maxpool + bias + relu -> emb1 (fp32 + bf16 hi/lo)
        const long row_img = (long)blockIdx.x * 2 + img;
        #pragma unroll
        for (int s = 0; s < 2; s++) {
            const int mt = mp * 2 + s;
            #pragma unroll
            for (int j = 0; j < 4; j++) {
                float v0 = fmaxf(acc[s][j][0], acc[s][j][2]);
                float v1 = fmaxf(acc[s][j][1], acc[s][j][3]);
                const float u0 = fmaxf(v0, __shfl_down_sync(0xffffffffu, v0, 4));
                const float u1 = fmaxf(v1, __shfl_down_sync(0xffffffffu, v1, 4));
                if (((l >> 2) & 1) == 0) {
                    const int pc = l >> 3;
                    const int p  = mt * 4 + pc;
                    const int nn = nh * 32 + j * 8 + 2 * (l & 3);
                    float2 o;
                    o.x = fmaxf(u0 + b2[nn], 0.f);
                    o.y = fmaxf(u1 + b2[nn + 1], 0.f);
                    const long base = row_img * DIM + p * 64 + nn;
                    *(float2*)&g_emb1[base] = o;
                    const __nv_bfloat16 h0 = __float2bfloat16(o.x);
                    const __nv_bfloat16 h1 = __float2bfloat16(o.y);
                    __nv_bfloat162 hh; hh.x = h0; hh.y = h1;
                    __nv_bfloat162 ll;
                    ll.x = __float2bfloat16(o.x - __bfloat162float(h0));
                    ll.y = __float2bfloat16(o.y - __bfloat162float(h1));
                    *(__nv_bfloat162*)&g_emb1h[base] = hh;
                    *(__nv_bfloat162*)&g_emb1l[base] = ll;
                }
            }
        }
    }
}

// ---------------------------------------------------------------------------
// Tensor-core attention: CTA = 64 rows x 256 units; warps m32 x n64
// (2 m-halves x 4 n-quarters). 2 CTAs/SM.
// smem: Ah@0(9216) Al@9216 Bh@18432(36864) Bl@55296 sb@92160 sv@93184 wred@94208
// ---------------------------------------------------------------------------
#define ATT_SMEM 95232

__global__ __launch_bounds__(256, 2) void att_mma_kernel(
    int lvl, const float* __restrict__ b, const float* __restrict__ v,
    const float* __restrict__ vb)
{
    extern __shared__ char sm[];
    const unsigned sb32 = (unsigned)__cvta_generic_to_shared(sm);
    const int tid = threadIdx.x;
    const int row0 = blockIdx.x * 64;

    const __nv_bfloat16* eh = lvl == 0 ? g_emb1h : (lvl == 1 ? g_emb2h : g_emb3h);
    const __nv_bfloat16* el = lvl == 0 ? g_emb1l : (lvl == 1 ? g_emb2l : g_emb3l);
    const __nv_bfloat16* wh = g_awt_hi + (size_t)lvl * (NATT * DIM);
    const __nv_bfloat16* wl = g_awt_lo + (size_t)lvl * (NATT * DIM);
    float* s_out = s_buf(lvl);

    float* sbf  = (float*)(sm + 92160);
    float* svf  = (float*)(sm + 93184);
    float* wred = (float*)(sm + 94208);   // [64 rows][4 quarters]
    sbf[tid] = b[tid];
    svf[tid] = v[tid];

    const int l  = tid & 31, w = tid >> 5;
    const int mp = w >> 2;     // m half (rows 0-31 / 32-63)
    const int nq = w & 3;      // n quarter (64 cols)
    const int lane_r = ((l >> 3) & 1) * 8 + (l & 7);
    const unsigned khalf = ((l >> 4) & 1) * 16;

    float acc[2][8][4];
    #pragma unroll
    for (int s = 0; s < 2; s++)
        #pragma unroll
        for (int j = 0; j < 8; j++)
            #pragma unroll
            for (int q = 0; q < 4; q++) acc[s][j][q] = 0.f;

    for (int kc = 0; kc < 16; kc++) {
        __syncthreads();
        const int k0 = kc * 64;
        for (int i = tid; i < 1024; i += 256) {
            const int pl = i >> 9, ii = i & 511;
            const int r = ii >> 3, c = ii & 7;
            const __nv_bfloat16* src =
                (pl ? el : eh) + (size_t)(row0 + r) * DIM + k0 + c * 8;
            *(uint4*)(sm + pl * 9216 + r * 144 + c * 16) = *(const uint4*)src;
        }
        for (int i = tid; i < 4096; i += 256) {
            const int pl = i >> 11, ii = i & 2047;
            const int n = ii >> 3, c = ii & 7;
            const __nv_bfloat16* src =
                (pl ? wl : wh) + (size_t)n * DIM + k0 + c * 8;
            *(uint4*)(sm + 18432 + pl * 36864 + n * 144 + c * 16) = *(const uint4*)src;
        }
        __syncthreads();

        #pragma unroll
        for (int ks = 0; ks < 4; ks++) {
            unsigned ah[2][4], al[2][4];
            #pragma unroll
            for (int s = 0; s < 2; s++) {
                const unsigned aoff =
                    (unsigned)(mp * 32 + s * 16 + lane_r) * 144 + ks * 32 + khalf;
                ldsm4(ah[s][0], ah[s][1], ah[s][2], ah[s][3], sb32 + aoff);
                ldsm4(al[s][0], al[s][1], al[s][2], al[s][3], sb32 + 9216 + aoff);
            }
            #pragma unroll
            for (int g = 0; g < 2; g++) {
                const unsigned boff =
                    (unsigned)(nq * 64 + g * 32 + l) * 144 + ks * 32;
                unsigned b0h[4], b1h[4], b0l[4], b1l[4];
                ldsm4(b0h[0], b0h[1], b0h[2], b0h[3], sb32 + 18432 + boff);
                ldsm4(b1h[0], b1h[1], b1h[2], b1h[3], sb32 + 18432 + boff + 16);
                ldsm4(b0l[0], b0l[1], b0l[2], b0l[3], sb32 + 55296 + boff);
                ldsm4(b1l[0], b1l[1], b1l[2], b1l[3], sb32 + 55296 + boff + 16);
                #pragma unroll
                for (int s = 0; s < 2; s++) {
                    #pragma unroll
                    for (int jj = 0; jj < 4; jj++) {
                        float* c = acc[s][g * 4 + jj];
                        mma_bf16(c, ah[s][0], ah[s][1], ah[s][2], ah[s][3],
                                 b0h[jj], b1h[jj]);
                        mma_bf16(c, ah[s][0], ah[s][1], ah[s][2], ah[s][3],
                                 b0l[jj], b1l[jj]);
                        mma_bf16(c, al[s][0], al[s][1], al[s][2], al[s][3],
                                 b0h[jj], b1h[jj]);
                    }
                }
            }
        }
    }

    // epilogue: tanh(h+b)*v, reduce over n -> per-row partials
    #pragma unroll
    for (int s = 0; s < 2; s++) {
        float pvA = 0.f, pvB = 0.f;
        #pragma unroll
        for (int j = 0; j < 8; j++) {
            const int n = nq * 64 + j * 8 + (l & 3) * 2;
            const float b0v = sbf[n], b1v = sbf[n + 1];
            const float v0 = svf[n], v1 = svf[n + 1];
            pvA += tanhf(acc[s][j][0] + b0v) * v0 + tanhf(acc[s][j][1] + b1v) * v1;
            pvB += tanhf(acc[s][j][2] + b0v) * v0 + tanhf(acc[s][j][3] + b1v) * v1;
        }
        pvA += __shfl_xor_sync(0xffffffffu, pvA, 1);
        pvA += __shfl_xor_sync(0xffffffffu, pvA, 2);
        pvB += __shfl_xor_sync(0xffffffffu, pvB, 1);
        pvB += __shfl_xor_sync(0xffffffffu, pvB, 2);
        if ((l & 3) == 0) {
            const int r = mp * 32 + s * 16 + (l >> 2);
            wred[r * 4 + nq]       = pvA;
            wred[(r + 8) * 4 + nq] = pvB;
        }
    }
    __syncthreads();
    if (tid < 64) {
        const float z = wred[tid * 4] + wred[tid * 4 + 1] +
                        wred[tid * 4 + 2] + wred[tid * 4 + 3] + vb[0];
        s_out[row0 + tid] = 1.f / (1.f + expf(-z));
    }
}

// ---------------------------------------------------------------------------
__global__ __launch_bounds__(1024) void stats_kernel(int lvl, int R)
{
    __shared__ float red[1024];
    const float* s = s_buf(lvl);
    const int tid = threadIdx.x;

    float m = -1e30f;
    for (int i = tid; i < R; i += 1024) m = fmaxf(m, s[i]);
    red[tid] = m; __syncthreads();
    for (int off = 512; off; off >>= 1) {
        if (tid < off) red[tid] = fmaxf(red[tid], red[tid + off]);
        __syncthreads();
    }
    const float mx = red[0];
    __syncthreads();

    float sum = 0.f;
    for (int i = tid; i < R; i += 1024) sum += expf(s[i] - mx);
    red[tid] = sum; __syncthreads();
    for (int off = 512; off; off >>= 1) {
        if (tid < off) red[tid] += red[tid + off];
        __syncthreads();
    }
    if (tid == 0) { g_stats[lvl * 2] = mx; g_stats[lvl * 2 + 1] = red[0]; }
}

// ---------------------------------------------------------------------------
__global__ __launch_bounds__(256) void segsum_kernel(int lvl)
{
    __shared__ float ws[16];
    const float* ein  = emb_buf(lvl);
    float*       eout = emb_buf(lvl + 1);
    __nv_bfloat16* eouth = lvl == 0 ? g_emb2h : g_emb3h;
    __nv_bfloat16* eoutl = lvl == 0 ? g_emb2l : g_emb3l;
    const float* s    = s_buf(lvl);
    const int bg = blockIdx.x, tid = threadIdx.x;

    if (tid < 16) {
        const float mx = g_stats[lvl * 2];
        const float inv = 1.f / g_stats[lvl * 2 + 1];
        ws[tid] = expf(s[bg * 16 + tid] - mx) * inv;
    }
    __syncthreads();

    const float4* base = (const float4*)(ein + (long)bg * 16 * DIM);
    float4* dst = (float4*)(eout + (long)bg * DIM);
    for (int d = tid; d < DIM / 4; d += 256) {
        float4 a = make_float4(0.f, 0.f, 0.f, 0.f);
        #pragma unroll
        for (int i = 0; i < 16; i++) {
            const float w = ws[i];
            const float4 e = base[i * (DIM / 4) + d];
            a.x += w * e.x; a.y += w * e.y; a.z += w * e.z; a.w += w * e.w;
        }
        dst[d] = a;
        const long eb = (long)bg * DIM + d * 4;
        float av[4] = {a.x, a.y, a.z, a.w};
        #pragma unroll
        for (int q = 0; q < 4; q++) {
            const __nv_bfloat16 h = __float2bfloat16(av[q]);
            eouth[eb + q] = h;
            eoutl[eb + q] = __float2bfloat16(av[q] - __bfloat162float(h));
        }
    }
}

// ---------------------------------------------------------------------------
__global__ __launch_bounds__(512) void final_kernel(
    const float* __restrict__ clsW, const float* __restrict__ clsb,
    const float* __restrict__ outW, const float* __restrict__ outb,
    float* __restrict__ out)
{
    __shared__ float w3[64];
    __shared__ float outer[DIM];
    __shared__ float red[512];
    const int tid = threadIdx.x;
    const float* s3 = s_buf(2);

    if (tid == 0) {
        float mx = -1e30f;
        for (int i = 0; i < 64; i++) mx = fmaxf(mx, s3[i]);
        float sum = 0.f;
        for (int i = 0; i < 64; i++) { float e = expf(s3[i] - mx); w3[i] = e; sum += e; }
        const float inv = 1.f / sum;
        for (int i = 0; i < 64; i++) w3[i] *= inv;
    }
    __syncthreads();

    for (int d = tid; d < DIM; d += 512) {
        float acc = 0.f;
        #pragma unroll 8
        for (int b2 = 0; b2 < 64; b2++) acc += w3[b2] * g_emb3[b2 * DIM + d];
        outer[d] = acc;
    }
    __syncthreads();

    float acc = 0.f;
    const float* wp = clsW + tid;
    for (int d = 0; d < DIM; d++) acc += outer[d] * wp[d * NCLS];
    red[tid] = (acc + clsb[tid]) * outW[tid];
    __syncthreads();
    for (int off = 256; off; off >>= 1) {
        if (tid < off) red[tid] += red[tid + off];
        __syncthreads();
    }
    if (tid == 0) out[0] = 1.f / (1.f + expf(-(red[0] + outb[0])));
}

// ---------------------------------------------------------------------------
extern "C" void kernel_launch(void* const* d_in, const int* in_sizes, int n_in,
                              void* d_out, int out_size)
{
    const float* x    = (const float*)d_in[0];
    const float* c1w  = (const float*)d_in[1];
    const float* c1b  = (const float*)d_in[2];
    const float* c2w  = (const float*)d_in[3];
    const float* c2b  = (const float*)d_in[4];
    const float* a1W  = (const float*)d_in[5];
    const float* a1b  = (const float*)d_in[6];
    const float* a1v  = (const float*)d_in[7];
    const float* a1vb = (const float*)d_in[8];
    const float* a2W  = (const float*)d_in[9];
    const float* a2b  = (const float*)d_in[10];
    const float* a2v  = (const float*)d_in[11];
    const float* a2vb = (const float*)d_in[12];
    const float* a3W  = (const float*)d_in[13];
    const float* a3b  = (const float*)d_in[14];
    const float* a3v  = (const float*)d_in[15];
    const float* a3vb = (const float*)d_in[16];
    const float* clsW = (const float*)d_in[17];
    const float* clsb = (const float*)d_in[18];
    const float* outW = (const float*)d_in[19];
    const float* outb = (const float*)d_in[20];

    cudaFuncSetAttribute(fused_conv_kernel,
                         cudaFuncAttributeMaxDynamicSharedMemorySize, FC_SMEM);
    cudaFuncSetAttribute(att_mma_kernel,
                         cudaFuncAttributeMaxDynamicSharedMemorySize, ATT_SMEM);

    prep_w2t<<<200, 256>>>(c2w);
    prep_awt_all<<<3072, 256>>>(a1W, a2W, a3W);

    fused_conv_kernel<<<N_INST / 2, 256, FC_SMEM>>>(x, c1w, c1b, c2b);

    att_mma_kernel<<<N_INST / 64, 256, ATT_SMEM>>>(0, a1b, a1v, a1vb);
    stats_kernel<<<1, 1024>>>(0, N_INST);
    segsum_kernel<<<NB1, 256>>>(0);

    att_mma_kernel<<<NB1 / 64, 256, ATT_SMEM>>>(1, a2b, a2v, a2vb);
    stats_kernel<<<1, 1024>>>(1, NB1);
    segsum_kernel<<<NB2, 256>>>(1);

    att_mma_kernel<<<NB2 / 64, 256, ATT_SMEM>>>(2, a3b, a3v, a3vb);
    final_kernel<<<1, 512>>>(clsW, clsb, outW, outb, (float*)d_out);
}

// round 10
// speedup vs baseline: 1.6989x; 1.2624x over previous
#include <cuda_runtime.h>
#include <cuda_fp16.h>
#include <math.h>

#define N_INST 16384
#define NB1    1024
#define NB2    64
#define DIM    1024
#define NATT   256
#define NCLS   512

// ---------------- scratch (device globals; no allocation allowed) ----------
__device__ float g_emb1[N_INST * DIM];   // 64 MB (fp32 for segsum accuracy)
__device__ float g_emb2[NB1 * DIM];
__device__ float g_emb3[NB2 * DIM];
__device__ float g_s[N_INST + NB1 + NB2];
__device__ float g_stats[8];
// conv2 weights, transposed [n=64][k=800], split fp16 hi/lo
__device__ __half g_w2t_hi[64 * 800];
__device__ __half g_w2t_lo[64 * 800];
// embeddings as single fp16 (A-side of attention GEMMs)
__device__ __half g_emb1f16[N_INST * DIM];
__device__ __half g_emb2f16[NB1 * DIM];
__device__ __half g_emb3f16[NB2 * DIM];
// attention weights, transposed [n=256][k=1024], fp16 hi/lo, 3 levels
__device__ __half g_awt_hi[3 * NATT * DIM];
__device__ __half g_awt_lo[3 * NATT * DIM];

__device__ __forceinline__ float* emb_buf(int lvl) {
    return lvl == 0 ? g_emb1 : (lvl == 1 ? g_emb2 : g_emb3);
}
__device__ __forceinline__ float* s_buf(int lvl) {
    return lvl == 0 ? g_s : (lvl == 1 ? g_s + N_INST : g_s + N_INST + NB1);
}

// ---------------- mma helpers ----------------------------------------------
__device__ __forceinline__ void ldsm4(unsigned& r0, unsigned& r1, unsigned& r2,
                                      unsigned& r3, unsigned a) {
    asm volatile("ldmatrix.sync.aligned.m8n8.x4.shared.b16 {%0,%1,%2,%3}, [%4];"
                 : "=r"(r0), "=r"(r1), "=r"(r2), "=r"(r3) : "r"(a));
}
__device__ __forceinline__ void mma_f16(float* c, unsigned a0, unsigned a1,
                                        unsigned a2, unsigned a3,
                                        unsigned b0, unsigned b1) {
    asm volatile(
        "mma.sync.aligned.m16n8k16.row.col.f32.f16.f16.f32 "
        "{%0,%1,%2,%3},{%4,%5,%6,%7},{%8,%9},{%0,%1,%2,%3};"
        : "+f"(c[0]), "+f"(c[1]), "+f"(c[2]), "+f"(c[3])
        : "r"(a0), "r"(a1), "r"(a2), "r"(a3), "r"(b0), "r"(b1));
}

// ---------------------------------------------------------------------------
// Prep kernels: weight transposes + fp16 hi/lo splits
// ---------------------------------------------------------------------------
__global__ __launch_bounds__(256) void prep_w2t(const float* __restrict__ w2) {
    const int idx = blockIdx.x * 256 + threadIdx.x;
    if (idx >= 64 * 800) return;
    const int n = idx / 800, k = idx - n * 800;
    const float v = w2[k * 64 + n];
    const __half h = __float2half(v);
    g_w2t_hi[idx] = h;
    g_w2t_lo[idx] = __float2half(v - __half2float(h));
}

__global__ __launch_bounds__(256) void prep_awt_all(
    const float* __restrict__ W0, const float* __restrict__ W1,
    const float* __restrict__ W2)
{
    const int gidx = blockIdx.x * 256 + threadIdx.x;   // 3*262144
    const int set = gidx >> 18;
    const int idx = gidx & 262143;
    const float* W = set == 0 ? W0 : (set == 1 ? W1 : W2);
    const int n = idx >> 10, k = idx & 1023;
    const float v = W[k * NATT + n];
    const __half h = __float2half(v);
    g_awt_hi[set * (NATT * DIM) + idx] = h;
    g_awt_lo[set * (NATT * DIM) + idx] = __float2half(v - __half2float(h));
}

// ---------------------------------------------------------------------------
// Fused conv kernel: one CTA = 2 images; 2 CTAs/SM.
// Phase A scalar fp32 conv1 -> p1 stored as SINGLE fp16 plane.
// Phase B conv2 implicit GEMM, fp16 2-term (Ah*Bh + Ah*Bl).
// smem: p1[2 img][144*40 fp16] @0 (23040)
//       staging  @23040: PhaseA 9600 B | PhaseB slabs hi@23040 lo@44544
// ---------------------------------------------------------------------------
#define FC_SMEM 66048

__global__ __launch_bounds__(256, 2) void fused_conv_kernel(
    const float* __restrict__ x,
    const float* __restrict__ w1, const float* __restrict__ b1,
    const float* __restrict__ b2)
{
    extern __shared__ char smem[];
    const unsigned sbase = (unsigned)__cvta_generic_to_shared(smem);
    const int tid = threadIdx.x;

    __half* p1 = (__half*)smem;             // [img][144*40]

    // ---------------- Phase A: conv1 + relu + pool (scalar fp32) ----------
    {
        float* stg  = (float*)(smem + 23040);
        float* w1_s = stg;          // 800
        float* b1_s = stg + 800;    // 32
        float* in_s = stg + 832;    // 2 x 784
        for (int i = tid; i < 800; i += 256) w1_s[i] = w1[i];
        if (tid < 32) b1_s[tid] = b1[tid];
        const float* x0 = x + (size_t)blockIdx.x * 2 * 784;
        for (int i = tid; i < 1568; i += 256) in_s[i] = x0[i];
        __syncthreads();

        for (int t = tid; t < 2304; t += 256) {
            const int img = t >= 1152;
            const int tt  = t - img * 1152;
            const float* in = in_s + img * 784;
            const int c0 = (tt & 7) * 4;
            const int p  = tt >> 3;
            const int pr = p / 12, pc = p % 12;
            const int y0 = pr * 2, xx0 = pc * 2;
            float acc[4][4];
            #pragma unroll
            for (int j = 0; j < 4; j++)
                #pragma unroll
                for (int ch = 0; ch < 4; ch++) acc[j][ch] = 0.f;

            for (int ky = 0; ky < 5; ky++) {
                #pragma unroll
                for (int kx = 0; kx < 5; kx++) {
                    const float4 wv = *(const float4*)&w1_s[(ky * 5 + kx) * 32 + c0];
                    #pragma unroll
                    for (int j = 0; j < 4; j++) {
                        const int dy = j >> 1, dx = j & 1;
                        const float iv = in[(y0 + dy + ky) * 28 + (xx0 + dx + kx)];
                        acc[j][0] += iv * wv.x; acc[j][1] += iv * wv.y;
                        acc[j][2] += iv * wv.z; acc[j][3] += iv * wv.w;
                    }
                }
            }
            __half* ph = p1 + img * 5760 + p * 40 + c0;
            #pragma unroll
            for (int ch = 0; ch < 4; ch++) {
                float m = fmaxf(fmaxf(acc[0][ch], acc[1][ch]),
                                fmaxf(acc[2][ch], acc[3][ch]));
                const float v = fmaxf(m + b1_s[c0 + ch], 0.f);
                ph[ch] = __float2half(v);
            }
        }
    }

    // ---------------- Phase B: conv2 via fp16 tensor-core GEMM ------------
    // 8 warps = 2 img x 2 m-pairs x 2 n-halves; each warp m32 x n32.
    {
        const int l   = tid & 31;
        const int w   = tid >> 5;
        const int img = w >> 2;
        const int mp  = (w >> 1) & 1;
        const int nh  = w & 1;

        const int lane_r = ((l >> 3) & 1) * 8 + (l & 7);
        const unsigned khalf = ((l >> 4) & 1) * 16;

        unsigned abase[2];
        #pragma unroll
        for (int s = 0; s < 2; s++) {
            const int pos = (mp * 2 + s) * 16 + lane_r;
            abase[s] = (unsigned)(((pos >> 3) * 12 + (pos & 7)) * 80);
        }

        const unsigned aHb = sbase + img * 11520;
        const unsigned BHb = sbase + 23040;
        const unsigned BLb = sbase + 44544;

        float acc[2][4][4];
        #pragma unroll
        for (int s = 0; s < 2; s++)
            #pragma unroll
            for (int j = 0; j < 4; j++)
                #pragma unroll
                for (int q = 0; q < 4; q++) acc[s][j][q] = 0.f;

        const char* wth = (const char*)g_w2t_hi;
        const char* wtl = (const char*)g_w2t_lo;

        for (int ky = 0; ky < 5; ky++) {
            __syncthreads();   // previous slab (or phase-A staging) consumed
            for (int i = tid; i < 2560; i += 256) {
                const int s  = i >= 1280;
                const int ii = i - s * 1280;
                const int n  = ii / 20, c = ii - n * 20;
                const char* src = (s ? wtl : wth) + n * 1600 + ky * 320 + c * 16;
                char* dst = smem + 23040 + s * 21504 + n * 336 + c * 16;
                *(uint4*)dst = *(const uint4*)src;
            }
            __syncthreads();

            const unsigned kyoff = (unsigned)ky * 960;
            for (int kx = 0; kx < 5; kx++) {
                #pragma unroll
                for (int hf = 0; hf < 2; hf++) {
                    const unsigned kb = (unsigned)(kx * 2 + hf) * 32;
                    const unsigned brow = (unsigned)(nh * 32 + l) * 336 + kb;
                    unsigned bh[8], bl[8];
                    ldsm4(bh[0], bh[1], bh[2], bh[3], BHb + brow);
                    ldsm4(bh[4], bh[5], bh[6], bh[7], BHb + brow + 16);
                    ldsm4(bl[0], bl[1], bl[2], bl[3], BLb + brow);
                    ldsm4(bl[4], bl[5], bl[6], bl[7], BLb + brow + 16);

                    #pragma unroll
                    for (int s = 0; s < 2; s++) {
                        const unsigned ab =
                            abase[s] + kyoff + kx * 80 + khalf + hf * 32;
                        unsigned ah0, ah1, ah2, ah3;
                        ldsm4(ah0, ah1, ah2, ah3, aHb + ab);
                        #pragma unroll
                        for (int j = 0; j < 4; j++) {
                            mma_f16(acc[s][j], ah0, ah1, ah2, ah3, bh[j], bh[4 + j]);
                            mma_f16(acc[s][j], ah0, ah1, ah2, ah3, bl[j], bl[4 + j]);
                        }
                    }
                }
            }
        }

        // epilogue: 2x2 maxpool + bias + relu -> emb1 (fp32 + fp16)
        const long row_img = (long)blockIdx.x * 2 + img;
        #pragma unroll
        for (int s = 0; s < 2; s++) {
            const int mt = mp * 2 + s;
            #pragma unroll
            for (int j = 0; j < 4; j++) {
                float v0 = fmaxf(acc[s][j][0], acc[s][j][2]);
                float v1 = fmaxf(acc[s][j][1], acc[s][j][3]);
                const float u0 = fmaxf(v0, __shfl_down_sync(0xffffffffu, v0, 4));
                const float u1 = fmaxf(v1, __shfl_down_sync(0xffffffffu, v1, 4));
                if (((l >> 2) & 1) == 0) {
                    const int pc = l >> 3;
                    const int p  = mt * 4 + pc;
                    const int nn = nh * 32 + j * 8 + 2 * (l & 3);
                    float2 o;
                    o.x = fmaxf(u0 + b2[nn], 0.f);
                    o.y = fmaxf(u1 + b2[nn + 1], 0.f);
                    const long base = row_img * DIM + p * 64 + nn;
                    *(float2*)&g_emb1[base] = o;
                    __half2 hh;
                    hh.x = __float2half(o.x);
                    hh.y = __float2half(o.y);
                    *(__half2*)&g_emb1f16[base] = hh;
                }
            }
        }
    }
}

// ---------------------------------------------------------------------------
// Tensor-core attention: CTA = 64 rows x 256 units; warps m32 x n64.
// A = emb single fp16 plane; B = weights fp16 hi/lo; 2-term mma.
// smem: A@0(9216) Bh@9216(36864) Bl@46080(36864) sb@82944 sv@83968 wred@84992
// ---------------------------------------------------------------------------
#define ATT_SMEM 86016

__global__ __launch_bounds__(256, 2) void att_mma_kernel(
    int lvl, const float* __restrict__ b, const float* __restrict__ v,
    const float* __restrict__ vb)
{
    extern __shared__ char sm[];
    const unsigned sb32 = (unsigned)__cvta_generic_to_shared(sm);
    const int tid = threadIdx.x;
    const int row0 = blockIdx.x * 64;

    const __half* ef = lvl == 0 ? g_emb1f16 : (lvl == 1 ? g_emb2f16 : g_emb3f16);
    const __half* wh = g_awt_hi + (size_t)lvl * (NATT * DIM);
    const __half* wl = g_awt_lo + (size_t)lvl * (NATT * DIM);
    float* s_out = s_buf(lvl);

    float* sbf  = (float*)(sm + 82944);
    float* svf  = (float*)(sm + 83968);
    float* wred = (float*)(sm + 84992);   // [64 rows][4 quarters]
    sbf[tid] = b[tid];
    svf[tid] = v[tid];

    const int l  = tid & 31, w = tid >> 5;
    const int mp = w >> 2;     // m half (rows 0-31 / 32-63)
    const int nq = w & 3;      // n quarter (64 cols)
    const int lane_r = ((l >> 3) & 1) * 8 + (l & 7);
    const unsigned khalf = ((l >> 4) & 1) * 16;

    float acc[2][8][4];
    #pragma unroll
    for (int s = 0; s < 2; s++)
        #pragma unroll
        for (int j = 0; j < 8; j++)
            #pragma unroll
            for (int q = 0; q < 4; q++) acc[s][j][q] = 0.f;

    for (int kc = 0; kc < 16; kc++) {
        __syncthreads();
        const int k0 = kc * 64;
        // stage A: 64 rows x 64 k fp16 (512 uint4)
        for (int i = tid; i < 512; i += 256) {
            const int r = i >> 3, c = i & 7;
            const __half* src = ef + (size_t)(row0 + r) * DIM + k0 + c * 8;
            *(uint4*)(sm + r * 144 + c * 16) = *(const uint4*)src;
        }
        // stage B: 256 n x 64 k, hi+lo (4096 uint4)
        for (int i = tid; i < 4096; i += 256) {
            const int pl = i >> 11, ii = i & 2047;
            const int n = ii >> 3, c = ii & 7;
            const __half* src = (pl ? wl : wh) + (size_t)n * DIM + k0 + c * 8;
            *(uint4*)(sm + 9216 + pl * 36864 + n * 144 + c * 16) = *(const uint4*)src;
        }
        __syncthreads();

        #pragma unroll
        for (int ks = 0; ks < 4; ks++) {
            unsigned ah[2][4];
            #pragma unroll
            for (int s = 0; s < 2; s++) {
                const unsigned aoff =
                    (unsigned)(mp * 32 + s * 16 + lane_r) * 144 + ks * 32 + khalf;
                ldsm4(ah[s][0], ah[s][1], ah[s][2], ah[s][3], sb32 + aoff);
            }
            #pragma unroll
            for (int g = 0; g < 2; g++) {
                const unsigned boff =
                    (unsigned)(nq * 64 + g * 32 + l) * 144 + ks * 32;
                unsigned b0h[4], b1h[4], b0l[4], b1l[4];
                ldsm4(b0h[0], b0h[1], b0h[2], b0h[3], sb32 + 9216 + boff);
                ldsm4(b1h[0], b1h[1], b1h[2], b1h[3], sb32 + 9216 + boff + 16);
                ldsm4(b0l[0], b0l[1], b0l[2], b0l[3], sb32 + 46080 + boff);
                ldsm4(b1l[0], b1l[1], b1l[2], b1l[3], sb32 + 46080 + boff + 16);
                #pragma unroll
                for (int s = 0; s < 2; s++) {
                    #pragma unroll
                    for (int jj = 0; jj < 4; jj++) {
                        float* c = acc[s][g * 4 + jj];
                        mma_f16(c, ah[s][0], ah[s][1], ah[s][2], ah[s][3],
                                b0h[jj], b1h[jj]);
                        mma_f16(c, ah[s][0], ah[s][1], ah[s][2], ah[s][3],
                                b0l[jj], b1l[jj]);
                    }
                }
            }
        }
    }

    // epilogue: tanh(h+b)*v, reduce over n -> per-row partials
    #pragma unroll
    for (int s = 0; s < 2; s++) {
        float pvA = 0.f, pvB = 0.f;
        #pragma unroll
        for (int j = 0; j < 8; j++) {
            const int n = nq * 64 + j * 8 + (l & 3) * 2;
            const float b0v = sbf[n], b1v = sbf[n + 1];
            const float v0 = svf[n], v1 = svf[n + 1];
            pvA += tanhf(acc[s][j][0] + b0v) * v0 + tanhf(acc[s][j][1] + b1v) * v1;
            pvB += tanhf(acc[s][j][2] + b0v) * v0 + tanhf(acc[s][j][3] + b1v) * v1;
        }
        pvA += __shfl_xor_sync(0xffffffffu, pvA, 1);
        pvA += __shfl_xor_sync(0xffffffffu, pvA, 2);
        pvB += __shfl_xor_sync(0xffffffffu, pvB, 1);
        pvB += __shfl_xor_sync(0xffffffffu, pvB, 2);
        if ((l & 3) == 0) {
            const int r = mp * 32 + s * 16 + (l >> 2);
            wred[r * 4 + nq]       = pvA;
            wred[(r + 8) * 4 + nq] = pvB;
        }
    }
    __syncthreads();
    if (tid < 64) {
        const float z = wred[tid * 4] + wred[tid * 4 + 1] +
                        wred[tid * 4 + 2] + wred[tid * 4 + 3] + vb[0];
        s_out[row0 + tid] = 1.f / (1.f + expf(-z));
    }
}

// ---------------------------------------------------------------------------
__global__ __launch_bounds__(1024) void stats_kernel(int lvl, int R)
{
    __shared__ float red[1024];
    const float* s = s_buf(lvl);
    const int tid = threadIdx.x;

    float m = -1e30f;
    for (int i = tid; i < R; i += 1024) m = fmaxf(m, s[i]);
    red[tid] = m; __syncthreads();
    for (int off = 512; off; off >>= 1) {
        if (tid < off) red[tid] = fmaxf(red[tid], red[tid + off]);
        __syncthreads();
    }
    const float mx = red[0];
    __syncthreads();

    float sum = 0.f;
    for (int i = tid; i < R; i += 1024) sum += expf(s[i] - mx);
    red[tid] = sum; __syncthreads();
    for (int off = 512; off; off >>= 1) {
        if (tid < off) red[tid] += red[tid + off];
        __syncthreads();
    }
    if (tid == 0) { g_stats[lvl * 2] = mx; g_stats[lvl * 2 + 1] = red[0]; }
}

// ---------------------------------------------------------------------------
// segsum: weighted bag pooling (fp32) + emit fp16 emb for next attention
// ---------------------------------------------------------------------------
__global__ __launch_bounds__(256) void segsum_kernel(int lvl)
{
    __shared__ float ws[16];
    const float* ein  = emb_buf(lvl);
    float*       eout = emb_buf(lvl + 1);
    __half* eoutf = lvl == 0 ? g_emb2f16 : g_emb3f16;
    const float* s    = s_buf(lvl);
    const int bg = blockIdx.x, tid = threadIdx.x;

    if (tid < 16) {
        const float mx = g_stats[lvl * 2];
        const float inv = 1.f / g_stats[lvl * 2 + 1];
        ws[tid] = expf(s[bg * 16 + tid] - mx) * inv;
    }
    __syncthreads();

    const float4* base = (const float4*)(ein + (long)bg * 16 * DIM);
    float4* dst = (float4*)(eout + (long)bg * DIM);
    for (int d = tid; d < DIM / 4; d += 256) {
        float4 a = make_float4(0.f, 0.f, 0.f, 0.f);
        #pragma unroll
        for (int i = 0; i < 16; i++) {
            const float w = ws[i];
            const float4 e = base[i * (DIM / 4) + d];
            a.x += w * e.x; a.y += w * e.y; a.z += w * e.z; a.w += w * e.w;
        }
        dst[d] = a;
        const long eb = (long)bg * DIM + d * 4;
        eoutf[eb + 0] = __float2half(a.x);
        eoutf[eb + 1] = __float2half(a.y);
        eoutf[eb + 2] = __float2half(a.z);
        eoutf[eb + 3] = __float2half(a.w);
    }
}

// ---------------------------------------------------------------------------
__global__ __launch_bounds__(512) void final_kernel(
    const float* __restrict__ clsW, const float* __restrict__ clsb,
    const float* __restrict__ outW, const float* __restrict__ outb,
    float* __restrict__ out)
{
    __shared__ float w3[64];
    __shared__ float outer[DIM];
    __shared__ float red[512];
    const int tid = threadIdx.x;
    const float* s3 = s_buf(2);

    if (tid == 0) {
        float mx = -1e30f;
        for (int i = 0; i < 64; i++) mx = fmaxf(mx, s3[i]);
        float sum = 0.f;
        for (int i = 0; i < 64; i++) { float e = expf(s3[i] - mx); w3[i] = e; sum += e; }
        const float inv = 1.f / sum;
        for (int i = 0; i < 64; i++) w3[i] *= inv;
    }
    __syncthreads();

    for (int d = tid; d < DIM; d += 512) {
        float acc = 0.f;
        #pragma unroll 8
        for (int b2 = 0; b2 < 64; b2++) acc += w3[b2] * g_emb3[b2 * DIM + d];
        outer[d] = acc;
    }
    __syncthreads();

    float acc = 0.f;
    const float* wp = clsW + tid;
    for (int d = 0; d < DIM; d++) acc += outer[d] * wp[d * NCLS];
    red[tid] = (acc + clsb[tid]) * outW[tid];
    __syncthreads();
    for (int off = 256; off; off >>= 1) {
        if (tid < off) red[tid] += red[tid + off];
        __syncthreads();
    }
    if (tid == 0) out[0] = 1.f / (1.f + expf(-(red[0] + outb[0])));
}

// ---------------------------------------------------------------------------
extern "C" void kernel_launch(void* const* d_in, const int* in_sizes, int n_in,
                              void* d_out, int out_size)
{
    const float* x    = (const float*)d_in[0];
    const float* c1w  = (const float*)d_in[1];
    const float* c1b  = (const float*)d_in[2];
    const float* c2w  = (const float*)d_in[3];
    const float* c2b  = (const float*)d_in[4];
    const float* a1W  = (const float*)d_in[5];
    const float* a1b  = (const float*)d_in[6];
    const float* a1v  = (const float*)d_in[7];
    const float* a1vb = (const float*)d_in[8];
    const float* a2W  = (const float*)d_in[9];
    const float* a2b  = (const float*)d_in[10];
    const float* a2v  = (const float*)d_in[11];
    const float* a2vb = (const float*)d_in[12];
    const float* a3W  = (const float*)d_in[13];
    const float* a3b  = (const float*)d_in[14];
    const float* a3v  = (const float*)d_in[15];
    const float* a3vb = (const float*)d_in[16];
    const float* clsW = (const float*)d_in[17];
    const float* clsb = (const float*)d_in[18];
    const float* outW = (const float*)d_in[19];
    const float* outb = (const float*)d_in[20];

    cudaFuncSetAttribute(fused_conv_kernel,
                         cudaFuncAttributeMaxDynamicSharedMemorySize, FC_SMEM);
    cudaFuncSetAttribute(att_mma_kernel,
                         cudaFuncAttributeMaxDynamicSharedMemorySize, ATT_SMEM);

    prep_w2t<<<200, 256>>>(c2w);
    prep_awt_all<<<3072, 256>>>(a1W, a2W, a3W);

    fused_conv_kernel<<<N_INST / 2, 256, FC_SMEM>>>(x, c1w, c1b, c2b);

    att_mma_kernel<<<N_INST / 64, 256, ATT_SMEM>>>(0, a1b, a1v, a1vb);
    stats_kernel<<<1, 1024>>>(0, N_INST);
    segsum_kernel<<<NB1, 256>>>(0);

    att_mma_kernel<<<NB1 / 64, 256, ATT_SMEM>>>(1, a2b, a2v, a2vb);
    stats_kernel<<<1, 1024>>>(1, NB1);
    segsum_kernel<<<NB2, 256>>>(1);

    att_mma_kernel<<<NB2 / 64, 256, ATT_SMEM>>>(2, a3b, a3v, a3vb);
    final_kernel<<<1, 512>>>(clsW, clsb, outW, outb, (float*)d_out);
}

// round 11
// speedup vs baseline: 2.4554x; 1.4453x over previous
#include <cuda_runtime.h>
#include <cuda_fp16.h>
#include <math.h>

#define N_INST 16384
#define NB1    1024
#define NB2    64
#define DIM    1024
#define NATT   256
#define NCLS   512

// ---------------- scratch (device globals; no allocation allowed) ----------
__device__ float g_emb1[N_INST * DIM];   // 64 MB (fp32 for segsum accuracy)
__device__ float g_emb2[NB1 * DIM];
__device__ float g_emb3[NB2 * DIM];
__device__ float g_s[N_INST + NB1 + NB2];
__device__ float g_stats[8];
// conv2 weights, transposed [n=64][k=800], fp16
__device__ __half g_w2t[64 * 800];
// embeddings as fp16 (A-side of attention GEMMs)
__device__ __half g_emb1f16[N_INST * DIM];
__device__ __half g_emb2f16[NB1 * DIM];
__device__ __half g_emb3f16[NB2 * DIM];
// attention weights, transposed [n=256][k=1024], fp16, 3 levels
__device__ __half g_awt[3 * NATT * DIM];

__device__ __forceinline__ float* emb_buf(int lvl) {
    return lvl == 0 ? g_emb1 : (lvl == 1 ? g_emb2 : g_emb3);
}
__device__ __forceinline__ float* s_buf(int lvl) {
    return lvl == 0 ? g_s : (lvl == 1 ? g_s + N_INST : g_s + N_INST + NB1);
}

// ---------------- mma helpers ----------------------------------------------
__device__ __forceinline__ void ldsm4(unsigned& r0, unsigned& r1, unsigned& r2,
                                      unsigned& r3, unsigned a) {
    asm volatile("ldmatrix.sync.aligned.m8n8.x4.shared.b16 {%0,%1,%2,%3}, [%4];"
                 : "=r"(r0), "=r"(r1), "=r"(r2), "=r"(r3) : "r"(a));
}
__device__ __forceinline__ void mma_f16(float* c, unsigned a0, unsigned a1,
                                        unsigned a2, unsigned a3,
                                        unsigned b0, unsigned b1) {
    asm volatile(
        "mma.sync.aligned.m16n8k16.row.col.f32.f16.f16.f32 "
        "{%0,%1,%2,%3},{%4,%5,%6,%7},{%8,%9},{%0,%1,%2,%3};"
        : "+f"(c[0]), "+f"(c[1]), "+f"(c[2]), "+f"(c[3])
        : "r"(a0), "r"(a1), "r"(a2), "r"(a3), "r"(b0), "r"(b1));
}

// ---------------------------------------------------------------------------
// Prep kernels: weight transposes to fp16
// ---------------------------------------------------------------------------
__global__ __launch_bounds__(256) void prep_w2t(const float* __restrict__ w2) {
    const int idx = blockIdx.x * 256 + threadIdx.x;
    if (idx >= 64 * 800) return;
    const int n = idx / 800, k = idx - n * 800;
    g_w2t[idx] = __float2half(w2[k * 64 + n]);
}

__global__ __launch_bounds__(256) void prep_awt_all(
    const float* __restrict__ W0, const float* __restrict__ W1,
    const float* __restrict__ W2)
{
    const int gidx = blockIdx.x * 256 + threadIdx.x;   // 3*262144
    const int set = gidx >> 18;
    const int idx = gidx & 262143;
    const float* W = set == 0 ? W0 : (set == 1 ? W1 : W2);
    const int n = idx >> 10, k = idx & 1023;
    g_awt[set * (NATT * DIM) + idx] = __float2half(W[k * NATT + n]);
}

// ---------------------------------------------------------------------------
// Fused conv kernel: one CTA = 2 images; 2 CTAs/SM.
// Phase A scalar fp32 conv1 -> p1 stored as fp16 plane.
// Phase B conv2 implicit GEMM, single-term fp16 mma.
// smem: p1[2 img][144*40 fp16] @0 (23040)
//       staging @23040: PhaseA 9600 B | PhaseB slab 21504 B
// ---------------------------------------------------------------------------
#define FC_SMEM 44544

__global__ __launch_bounds__(256, 2) void fused_conv_kernel(
    const float* __restrict__ x,
    const float* __restrict__ w1, const float* __restrict__ b1,
    const float* __restrict__ b2)
{
    extern __shared__ char smem[];
    const unsigned sbase = (unsigned)__cvta_generic_to_shared(smem);
    const int tid = threadIdx.x;

    __half* p1 = (__half*)smem;             // [img][144*40]

    // ---------------- Phase A: conv1 + relu + pool (scalar fp32) ----------
    {
        float* stg  = (float*)(smem + 23040);
        float* w1_s = stg;          // 800
        float* b1_s = stg + 800;    // 32
        float* in_s = stg + 832;    // 2 x 784
        for (int i = tid; i < 800; i += 256) w1_s[i] = w1[i];
        if (tid < 32) b1_s[tid] = b1[tid];
        const float* x0 = x + (size_t)blockIdx.x * 2 * 784;
        for (int i = tid; i < 1568; i += 256) in_s[i] = x0[i];
        __syncthreads();

        for (int t = tid; t < 2304; t += 256) {
            const int img = t >= 1152;
            const int tt  = t - img * 1152;
            const float* in = in_s + img * 784;
            const int c0 = (tt & 7) * 4;
            const int p  = tt >> 3;
            const int pr = p / 12, pc = p % 12;
            const int y0 = pr * 2, xx0 = pc * 2;
            float acc[4][4];
            #pragma unroll
            for (int j = 0; j < 4; j++)
                #pragma unroll
                for (int ch = 0; ch < 4; ch++) acc[j][ch] = 0.f;

            for (int ky = 0; ky < 5; ky++) {
                #pragma unroll
                for (int kx = 0; kx < 5; kx++) {
                    const float4 wv = *(const float4*)&w1_s[(ky * 5 + kx) * 32 + c0];
                    #pragma unroll
                    for (int j = 0; j < 4; j++) {
                        const int dy = j >> 1, dx = j & 1;
                        const float iv = in[(y0 + dy + ky) * 28 + (xx0 + dx + kx)];
                        acc[j][0] += iv * wv.x; acc[j][1] += iv * wv.y;
                        acc[j][2] += iv * wv.z; acc[j][3] += iv * wv.w;
                    }
                }
            }
            __half* ph = p1 + img * 5760 + p * 40 + c0;
            #pragma unroll
            for (int ch = 0; ch < 4; ch++) {
                float m = fmaxf(fmaxf(acc[0][ch], acc[1][ch]),
                                fmaxf(acc[2][ch], acc[3][ch]));
                const float v = fmaxf(m + b1_s[c0 + ch], 0.f);
                ph[ch] = __float2half(v);
            }
        }
    }

    // ---------------- Phase B: conv2 via fp16 tensor-core GEMM ------------
    // 8 warps = 2 img x 2 m-pairs x 2 n-halves; each warp m32 x n32.
    {
        const int l   = tid & 31;
        const int w   = tid >> 5;
        const int img = w >> 2;
        const int mp  = (w >> 1) & 1;
        const int nh  = w & 1;

        const int lane_r = ((l >> 3) & 1) * 8 + (l & 7);
        const unsigned khalf = ((l >> 4) & 1) * 16;

        unsigned abase[2];
        #pragma unroll
        for (int s = 0; s < 2; s++) {
            const int pos = (mp * 2 + s) * 16 + lane_r;
            abase[s] = (unsigned)(((pos >> 3) * 12 + (pos & 7)) * 80);
        }

        const unsigned aHb = sbase + img * 11520;
        const unsigned BHb = sbase + 23040;

        float acc[2][4][4];
        #pragma unroll
        for (int s = 0; s < 2; s++)
            #pragma unroll
            for (int j = 0; j < 4; j++)
                #pragma unroll
                for (int q = 0; q < 4; q++) acc[s][j][q] = 0.f;

        const char* wt = (const char*)g_w2t;

        for (int ky = 0; ky < 5; ky++) {
            __syncthreads();   // previous slab (or phase-A staging) consumed
            for (int i = tid; i < 1280; i += 256) {
                const int n = i / 20, c = i - n * 20;
                const char* src = wt + n * 1600 + ky * 320 + c * 16;
                char* dst = smem + 23040 + n * 336 + c * 16;
                *(uint4*)dst = *(const uint4*)src;
            }
            __syncthreads();

            const unsigned kyoff = (unsigned)ky * 960;
            for (int kx = 0; kx < 5; kx++) {
                #pragma unroll
                for (int hf = 0; hf < 2; hf++) {
                    const unsigned kb = (unsigned)(kx * 2 + hf) * 32;
                    const unsigned brow = (unsigned)(nh * 32 + l) * 336 + kb;
                    unsigned bh[8];
                    ldsm4(bh[0], bh[1], bh[2], bh[3], BHb + brow);
                    ldsm4(bh[4], bh[5], bh[6], bh[7], BHb + brow + 16);

                    #pragma unroll
                    for (int s = 0; s < 2; s++) {
                        const unsigned ab =
                            abase[s] + kyoff + kx * 80 + khalf + hf * 32;
                        unsigned ah0, ah1, ah2, ah3;
                        ldsm4(ah0, ah1, ah2, ah3, aHb + ab);
                        #pragma unroll
                        for (int j = 0; j < 4; j++)
                            mma_f16(acc[s][j], ah0, ah1, ah2, ah3, bh[j], bh[4 + j]);
                    }
                }
            }
        }

        // epilogue: 2x2 maxpool + bias + relu -> emb1 (fp32 + fp16)
        const long row_img = (long)blockIdx.x * 2 + img;
        #pragma unroll
        for (int s = 0; s < 2; s++) {
            const int mt = mp * 2 + s;
            #pragma unroll
            for (int j = 0; j < 4; j++) {
                float v0 = fmaxf(acc[s][j][0], acc[s][j][2]);
                float v1 = fmaxf(acc[s][j][1], acc[s][j][3]);
                const float u0 = fmaxf(v0, __shfl_down_sync(0xffffffffu, v0, 4));
                const float u1 = fmaxf(v1, __shfl_down_sync(0xffffffffu, v1, 4));
                if (((l >> 2) & 1) == 0) {
                    const int pc = l >> 3;
                    const int p  = mt * 4 + pc;
                    const int nn = nh * 32 + j * 8 + 2 * (l & 3);
                    float2 o;
                    o.x = fmaxf(u0 + b2[nn], 0.f);
                    o.y = fmaxf(u1 + b2[nn + 1], 0.f);
                    const long base = row_img * DIM + p * 64 + nn;
                    *(float2*)&g_emb1[base] = o;
                    __half2 hh;
                    hh.x = __float2half(o.x);
                    hh.y = __float2half(o.y);
                    *(__half2*)&g_emb1f16[base] = hh;
                }
            }
        }
    }
}

// ---------------------------------------------------------------------------
// Tensor-core attention: CTA = 64 rows x 256 units; warps m32 x n64.
// A = emb fp16; B = weights fp16; single-term mma.
// smem: A@0(9216) B@9216(36864) sb@46080 sv@47104 wred@48128
// ---------------------------------------------------------------------------
#define ATT_SMEM 49152

__global__ __launch_bounds__(256, 2) void att_mma_kernel(
    int lvl, const float* __restrict__ b, const float* __restrict__ v,
    const float* __restrict__ vb)
{
    extern __shared__ char sm[];
    const unsigned sb32 = (unsigned)__cvta_generic_to_shared(sm);
    const int tid = threadIdx.x;
    const int row0 = blockIdx.x * 64;

    const __half* ef = lvl == 0 ? g_emb1f16 : (lvl == 1 ? g_emb2f16 : g_emb3f16);
    const __half* wh = g_awt + (size_t)lvl * (NATT * DIM);
    float* s_out = s_buf(lvl);

    float* sbf  = (float*)(sm + 46080);
    float* svf  = (float*)(sm + 47104);
    float* wred = (float*)(sm + 48128);   // [64 rows][4 quarters]
    sbf[tid] = b[tid];
    svf[tid] = v[tid];

    const int l  = tid & 31, w = tid >> 5;
    const int mp = w >> 2;     // m half (rows 0-31 / 32-63)
    const int nq = w & 3;      // n quarter (64 cols)
    const int lane_r = ((l >> 3) & 1) * 8 + (l & 7);
    const unsigned khalf = ((l >> 4) & 1) * 16;

    float acc[2][8][4];
    #pragma unroll
    for (int s = 0; s < 2; s++)
        #pragma unroll
        for (int j = 0; j < 8; j++)
            #pragma unroll
            for (int q = 0; q < 4; q++) acc[s][j][q] = 0.f;

    for (int kc = 0; kc < 16; kc++) {
        __syncthreads();
        const int k0 = kc * 64;
        // stage A: 64 rows x 64 k fp16 (512 uint4)
        for (int i = tid; i < 512; i += 256) {
            const int r = i >> 3, c = i & 7;
            const __half* src = ef + (size_t)(row0 + r) * DIM + k0 + c * 8;
            *(uint4*)(sm + r * 144 + c * 16) = *(const uint4*)src;
        }
        // stage B: 256 n x 64 k (2048 uint4)
        for (int i = tid; i < 2048; i += 256) {
            const int n = i >> 3, c = i & 7;
            const __half* src = wh + (size_t)n * DIM + k0 + c * 8;
            *(uint4*)(sm + 9216 + n * 144 + c * 16) = *(const uint4*)src;
        }
        __syncthreads();

        #pragma unroll
        for (int ks = 0; ks < 4; ks++) {
            unsigned ah[2][4];
            #pragma unroll
            for (int s = 0; s < 2; s++) {
                const unsigned aoff =
                    (unsigned)(mp * 32 + s * 16 + lane_r) * 144 + ks * 32 + khalf;
                ldsm4(ah[s][0], ah[s][1], ah[s][2], ah[s][3], sb32 + aoff);
            }
            #pragma unroll
            for (int g = 0; g < 2; g++) {
                const unsigned boff =
                    (unsigned)(nq * 64 + g * 32 + l) * 144 + ks * 32;
                unsigned b0h[4], b1h[4];
                ldsm4(b0h[0], b0h[1], b0h[2], b0h[3], sb32 + 9216 + boff);
                ldsm4(b1h[0], b1h[1], b1h[2], b1h[3], sb32 + 9216 + boff + 16);
                #pragma unroll
                for (int s = 0; s < 2; s++) {
                    #pragma unroll
                    for (int jj = 0; jj < 4; jj++)
                        mma_f16(acc[s][g * 4 + jj],
                                ah[s][0], ah[s][1], ah[s][2], ah[s][3],
                                b0h[jj], b1h[jj]);
                }
            }
        }
    }

    // epilogue: tanh(h+b)*v, reduce over n -> per-row partials
    #pragma unroll
    for (int s = 0; s < 2; s++) {
        float pvA = 0.f, pvB = 0.f;
        #pragma unroll
        for (int j = 0; j < 8; j++) {
            const int n = nq * 64 + j * 8 + (l & 3) * 2;
            const float b0v = sbf[n], b1v = sbf[n + 1];
            const float v0 = svf[n], v1 = svf[n + 1];
            pvA += tanhf(acc[s][j][0] + b0v) * v0 + tanhf(acc[s][j][1] + b1v) * v1;
            pvB += tanhf(acc[s][j][2] + b0v) * v0 + tanhf(acc[s][j][3] + b1v) * v1;
        }
        pvA += __shfl_xor_sync(0xffffffffu, pvA, 1);
        pvA += __shfl_xor_sync(0xffffffffu, pvA, 2);
        pvB += __shfl_xor_sync(0xffffffffu, pvB, 1);
        pvB += __shfl_xor_sync(0xffffffffu, pvB, 2);
        if ((l & 3) == 0) {
            const int r = mp * 32 + s * 16 + (l >> 2);
            wred[r * 4 + nq]       = pvA;
            wred[(r + 8) * 4 + nq] = pvB;
        }
    }
    __syncthreads();
    if (tid < 64) {
        const float z = wred[tid * 4] + wred[tid * 4 + 1] +
                        wred[tid * 4 + 2] + wred[tid * 4 + 3] + vb[0];
        s_out[row0 + tid] = 1.f / (1.f + expf(-z));
    }
}

// ---------------------------------------------------------------------------
__global__ __launch_bounds__(1024) void stats_kernel(int lvl, int R)
{
    __shared__ float red[1024];
    const float* s = s_buf(lvl);
    const int tid = threadIdx.x;

    float m = -1e30f;
    for (int i = tid; i < R; i += 1024) m = fmaxf(m, s[i]);
    red[tid] = m; __syncthreads();
    for (int off = 512; off; off >>= 1) {
        if (tid < off) red[tid] = fmaxf(red[tid], red[tid + off]);
        __syncthreads();
    }
    const float mx = red[0];
    __syncthreads();

    float sum = 0.f;
    for (int i = tid; i < R; i += 1024) sum += expf(s[i] - mx);
    red[tid] = sum; __syncthreads();
    for (int off = 512; off; off >>= 1) {
        if (tid < off) red[tid] += red[tid + off];
        __syncthreads();
    }
    if (tid == 0) { g_stats[lvl * 2] = mx; g_stats[lvl * 2 + 1] = red[0]; }
}

// ---------------------------------------------------------------------------
// segsum: weighted bag pooling (fp32) + emit fp16 emb for next attention
// ---------------------------------------------------------------------------
__global__ __launch_bounds__(256) void segsum_kernel(int lvl)
{
    __shared__ float ws[16];
    const float* ein  = emb_buf(lvl);
    float*       eout = emb_buf(lvl + 1);
    __half* eoutf = lvl == 0 ? g_emb2f16 : g_emb3f16;
    const float* s    = s_buf(lvl);
    const int bg = blockIdx.x, tid = threadIdx.x;

    if (tid < 16) {
        const float mx = g_stats[lvl * 2];
        const float inv = 1.f / g_stats[lvl * 2 + 1];
        ws[tid] = expf(s[bg * 16 + tid] - mx) * inv;
    }
    __syncthreads();

    const float4* base = (const float4*)(ein + (long)bg * 16 * DIM);
    float4* dst = (float4*)(eout + (long)bg * DIM);
    for (int d = tid; d < DIM / 4; d += 256) {
        float4 a = make_float4(0.f, 0.f, 0.f, 0.f);
        #pragma unroll
        for (int i = 0; i < 16; i++) {
            const float w = ws[i];
            const float4 e = base[i * (DIM / 4) + d];
            a.x += w * e.x; a.y += w * e.y; a.z += w * e.z; a.w += w * e.w;
        }
        dst[d] = a;
        const long eb = (long)bg * DIM + d * 4;
        eoutf[eb + 0] = __float2half(a.x);
        eoutf[eb + 1] = __float2half(a.y);
        eoutf[eb + 2] = __float2half(a.z);
        eoutf[eb + 3] = __float2half(a.w);
    }
}

// ---------------------------------------------------------------------------
__global__ __launch_bounds__(512) void final_kernel(
    const float* __restrict__ clsW, const float* __restrict__ clsb,
    const float* __restrict__ outW, const float* __restrict__ outb,
    float* __restrict__ out)
{
    __shared__ float w3[64];
    __shared__ float outer[DIM];
    __shared__ float red[512];
    const int tid = threadIdx.x;
    const float* s3 = s_buf(2);

    if (tid == 0) {
        float mx = -1e30f;
        for (int i = 0; i < 64; i++) mx = fmaxf(mx, s3[i]);
        float sum = 0.f;
        for (int i = 0; i < 64; i++) { float e = expf(s3[i] - mx); w3[i] = e; sum += e; }
        const float inv = 1.f / sum;
        for (int i = 0; i < 64; i++) w3[i] *= inv;
    }
    __syncthreads();

    for (int d = tid; d < DIM; d += 512) {
        float acc = 0.f;
        #pragma unroll 8
        for (int b2 = 0; b2 < 64; b2++) acc += w3[b2] * g_emb3[b2 * DIM + d];
        outer[d] = acc;
    }
    __syncthreads();

    float acc = 0.f;
    const float* wp = clsW + tid;
    for (int d = 0; d < DIM; d++) acc += outer[d] * wp[d * NCLS];
    red[tid] = (acc + clsb[tid]) * outW[tid];
    __syncthreads();
    for (int off = 256; off; off >>= 1) {
        if (tid < off) red[tid] += red[tid + off];
        __syncthreads();
    }
    if (tid == 0) out[0] = 1.f / (1.f + expf(-(red[0] + outb[0])));
}

// ---------------------------------------------------------------------------
extern "C" void kernel_launch(void* const* d_in, const int* in_sizes, int n_in,
                              void* d_out, int out_size)
{
    const float* x    = (const float*)d_in[0];
    const float* c1w  = (const float*)d_in[1];
    const float* c1b  = (const float*)d_in[2];
    const float* c2w  = (const float*)d_in[3];
    const float* c2b  = (const float*)d_in[4];
    const float* a1W  = (const float*)d_in[5];
    const float* a1b  = (const float*)d_in[6];
    const float* a1v  = (const float*)d_in[7];
    const float* a1vb = (const float*)d_in[8];
    const float* a2W  = (const float*)d_in[9];
    const float* a2b  = (const float*)d_in[10];
    const float* a2v  = (const float*)d_in[11];
    const float* a2vb = (const float*)d_in[12];
    const float* a3W  = (const float*)d_in[13];
    const float* a3b  = (const float*)d_in[14];
    const float* a3v  = (const float*)d_in[15];
    const float* a3vb = (const float*)d_in[16];
    const float* clsW = (const float*)d_in[17];
    const float* clsb = (const float*)d_in[18];
    const float* outW = (const float*)d_in[19];
    const float* outb = (const float*)d_in[20];

    cudaFuncSetAttribute(fused_conv_kernel,
                         cudaFuncAttributeMaxDynamicSharedMemorySize, FC_SMEM);
    cudaFuncSetAttribute(att_mma_kernel,
                         cudaFuncAttributeMaxDynamicSharedMemorySize, ATT_SMEM);

    prep_w2t<<<200, 256>>>(c2w);
    prep_awt_all<<<3072, 256>>>(a1W, a2W, a3W);

    fused_conv_kernel<<<N_INST / 2, 256, FC_SMEM>>>(x, c1w, c1b, c2b);

    att_mma_kernel<<<N_INST / 64, 256, ATT_SMEM>>>(0, a1b, a1v, a1vb);
    stats_kernel<<<1, 1024>>>(0, N_INST);
    segsum_kernel<<<NB1, 256>>>(0);

    att_mma_kernel<<<NB1 / 64, 256, ATT_SMEM>>>(1, a2b, a2v, a2vb);
    stats_kernel<<<1, 1024>>>(1, NB1);
    segsum_kernel<<<NB2, 256>>>(1);

    att_mma_kernel<<<NB2 / 64, 256, ATT_SMEM>>>(2, a3b, a3v, a3vb);
    final_kernel<<<1, 512>>>(clsW, clsb, outW, outb, (float*)d_out);
}